// round 5
// baseline (speedup 1.0000x reference)
#include <cuda_runtime.h>
#include <cuda_bf16.h>
#include <math.h>
#include <stdint.h>

#define B_    8
#define N_    4096
#define CIN   256
#define CQK   32
#define NROWS (B_ * N_)   // 32768
#define KSPL  96          // split-K: [hi|lo|hi] x [hi|hi|lo]
#define NCHUNK (N_ / 128) // 32
#define LOG2E 1.4426950408889634f

// ---- scratch (device globals; no allocation allowed) ----
__device__ __nv_bfloat16 g_qs[NROWS * KSPL];   // 6 MB  [row][96], pre-scaled by log2e
__device__ __nv_bfloat16 g_ks[NROWS * KSPL];   // 6 MB  [row][96]
__device__ float g_vbar[NROWS];
__device__ float g_xbar[NROWS];
__device__ float g_wvbar[CIN];
__device__ float g_bvbar;

// =========================== PTX helpers ===================================
__device__ __forceinline__ uint32_t smem_u32(const void* p) {
    uint32_t a;
    asm("{ .reg .u64 t; cvta.to.shared.u64 t, %1; cvt.u32.u64 %0, t; }"
        : "=r"(a) : "l"(p));
    return a;
}
__device__ __forceinline__ void cp_async16(void* dst, const void* src) {
    uint32_t d = smem_u32(dst);
    asm volatile("cp.async.cg.shared.global [%0], [%1], 16;" :: "r"(d), "l"(src) : "memory");
}
#define CP_COMMIT()  asm volatile("cp.async.commit_group;" ::: "memory")
#define CP_WAIT(n)   asm volatile("cp.async.wait_group %0;" :: "n"(n) : "memory")

__device__ __forceinline__ void ldsm_x4(uint32_t& r0, uint32_t& r1,
                                        uint32_t& r2, uint32_t& r3, uint32_t a) {
    asm volatile("ldmatrix.sync.aligned.m8n8.x4.shared.b16 {%0,%1,%2,%3}, [%4];"
        : "=r"(r0), "=r"(r1), "=r"(r2), "=r"(r3) : "r"(a));
}
__device__ __forceinline__ void mma_bf16(float& d0, float& d1, float& d2, float& d3,
    uint32_t a0, uint32_t a1, uint32_t a2, uint32_t a3,
    uint32_t b0, uint32_t b1,
    float c0, float c1, float c2, float c3) {
    asm volatile("mma.sync.aligned.m16n8k16.row.col.f32.bf16.bf16.f32 "
        "{%0,%1,%2,%3},{%4,%5,%6,%7},{%8,%9},{%10,%11,%12,%13};"
        : "=f"(d0), "=f"(d1), "=f"(d2), "=f"(d3)
        : "r"(a0), "r"(a1), "r"(a2), "r"(a3), "r"(b0), "r"(b1),
          "f"(c0), "f"(c1), "f"(c2), "f"(c3));
}
__device__ __forceinline__ float ex2f(float x) {
    float r;
    asm("ex2.approx.f32 %0, %1;" : "=f"(r) : "f"(x));
    return r;
}

// =========================== prep kernel ===================================
__global__ void prep_kernel(const float* __restrict__ Wv,
                            const float* __restrict__ bv) {
    int i = threadIdx.x;
    float s = 0.f;
    #pragma unroll 4
    for (int j = 0; j < CIN; j++) s += Wv[i * CIN + j];
    g_wvbar[i] = s * (1.f / CIN);
    if (i == 0) {
        float t = 0.f;
        for (int j = 0; j < CIN; j++) t += bv[j];
        g_bvbar = t * (1.f / CIN);
    }
}

// ======================= Q/K projection GEMM (+ fused vbar/xbar) ===========
// C(32768 x 64) = x(32768 x 256) @ [Wq|Wk](256 x 64) + bias.
// Q scaled by log2e, then both split to bf16: g_qs=[hi|lo|hi], g_ks=[hi|hi|lo].
// Also: vbar[row] = x[row,:].wvbar + bvbar, xbar[row] = mean(x[row,:]).
__device__ __forceinline__ uint32_t pack_bf2(float a, float b) {
    __nv_bfloat162 t = __floats2bfloat162_rn(a, b);
    return *reinterpret_cast<uint32_t*>(&t);
}

__global__ __launch_bounds__(256) void qk_gemm(
    const float* __restrict__ x,
    const float* __restrict__ Wq, const float* __restrict__ bq,
    const float* __restrict__ Wk, const float* __restrict__ bk) {

    __shared__ __align__(16) float As[128][36];
    __shared__ __align__(16) float Bs[32][64];
    __shared__ float wv_s[CIN];

    const int tid = threadIdx.x;
    const int tx = tid & 15, ty = tid >> 4;
    const int m0 = blockIdx.x * 128;

    wv_s[tid] = g_wvbar[tid];

    float acc[8][4];
    #pragma unroll
    for (int i = 0; i < 8; i++)
        #pragma unroll
        for (int j = 0; j < 4; j++) acc[i][j] = 0.f;

    float sv = 0.f, sx = 0.f;
    const int srow = tid >> 1, scb = (tid & 1) * 16;

    for (int kt = 0; kt < CIN; kt += 32) {
        {
            int c4 = tid & 7, r0 = tid >> 3;
            #pragma unroll
            for (int p = 0; p < 4; p++) {
                int r = r0 + p * 32;
                *(float4*)(&As[r][c4 * 4]) =
                    *(const float4*)(x + (size_t)(m0 + r) * CIN + kt + c4 * 4);
            }
        }
        {
            int c4 = tid & 15, r0 = tid >> 4;
            #pragma unroll
            for (int p = 0; p < 2; p++) {
                int r = r0 + p * 16;
                float4 v;
                if (c4 < 8) v = *(const float4*)(Wq + (size_t)(kt + r) * CQK + c4 * 4);
                else        v = *(const float4*)(Wk + (size_t)(kt + r) * CQK + (c4 - 8) * 4);
                *(float4*)(&Bs[r][c4 * 4]) = v;
            }
        }
        __syncthreads();

        #pragma unroll
        for (int kk = 0; kk < 32; kk++) {
            float a[8];
            #pragma unroll
            for (int i = 0; i < 8; i++) a[i] = As[ty * 8 + i][kk];
            float4 bv4 = *(const float4*)(&Bs[kk][tx * 4]);
            #pragma unroll
            for (int i = 0; i < 8; i++) {
                acc[i][0] += a[i] * bv4.x;
                acc[i][1] += a[i] * bv4.y;
                acc[i][2] += a[i] * bv4.z;
                acc[i][3] += a[i] * bv4.w;
            }
        }

        // fused row-sum pass over the As tile (vbar / xbar)
        #pragma unroll
        for (int j = 0; j < 16; j++) {
            float xv = As[srow][scb + j];
            sx += xv;
            sv = fmaf(wv_s[kt + scb + j], xv, sv);
        }
        __syncthreads();
    }

    // vbar / xbar writeback (threads paired on bit 0)
    sv += __shfl_xor_sync(0xffffffffu, sv, 1);
    sx += __shfl_xor_sync(0xffffffffu, sx, 1);
    if ((tid & 1) == 0) {
        g_vbar[m0 + srow] = sv + g_bvbar;
        g_xbar[m0 + srow] = sx * (1.f / CIN);
    }

    const int c = tx * 4;
    const bool isQ = (c < 32);
    const int c0 = isQ ? c : c - 32;
    float4 bb = isQ ? *(const float4*)(bq + c0) : *(const float4*)(bk + c0);
    const float scale = isQ ? LOG2E : 1.f;

    #pragma unroll
    for (int i = 0; i < 8; i++) {
        size_t row = (size_t)m0 + ty * 8 + i;
        float v0 = (acc[i][0] + bb.x) * scale, v1 = (acc[i][1] + bb.y) * scale;
        float v2 = (acc[i][2] + bb.z) * scale, v3 = (acc[i][3] + bb.w) * scale;
        __nv_bfloat16 h0 = __float2bfloat16_rn(v0), h1 = __float2bfloat16_rn(v1);
        __nv_bfloat16 h2 = __float2bfloat16_rn(v2), h3 = __float2bfloat16_rn(v3);
        float l0 = v0 - __bfloat162float(h0), l1 = v1 - __bfloat162float(h1);
        float l2 = v2 - __bfloat162float(h2), l3 = v3 - __bfloat162float(h3);
        uint2 hi = make_uint2(pack_bf2(v0, v1), pack_bf2(v2, v3));
        uint2 lo = make_uint2(pack_bf2(l0, l1), pack_bf2(l2, l3));
        if (isQ) {
            __nv_bfloat16* dst = g_qs + row * KSPL + c0;
            *(uint2*)(dst)      = hi;   // q_hi
            *(uint2*)(dst + 32) = lo;   // q_lo
            *(uint2*)(dst + 64) = hi;   // q_hi
        } else {
            __nv_bfloat16* dst = g_ks + row * KSPL + c0;
            *(uint2*)(dst)      = hi;   // k_hi
            *(uint2*)(dst + 32) = hi;   // k_hi
            *(uint2*)(dst + 64) = lo;   // k_lo
        }
    }
}

// =========================== attention kernel ==============================
// smem K tiles: [128 rows][104 bf16] (208-B pitch -> conflict-free ldmatrix)
#define TPITCH   208
#define TILE_B   (128 * TPITCH)      // 26624
#define OFF_VB   0                   // 16 KB vbar
#define OFF_K0   16384
#define OFF_K1   (OFF_K0 + TILE_B)   // 43008
#define SMEM_TOT (OFF_K1 + TILE_B)   // 69632

__global__ __launch_bounds__(256, 2) void attn_kernel(
    const float* __restrict__ gamma, float* __restrict__ out) {

    extern __shared__ __align__(16) char smem[];
    const uint32_t sb = smem_u32(smem);
    const int tid = threadIdx.x, wid = tid >> 5, lane = tid & 31;
    const int b = blockIdx.y, n0 = blockIdx.x * 128;

    // per-thread cp.async offsets for a 128x96 bf16 tile (1536 16B segs, 6/thread)
    int boff[6]; long soff[6];
    #pragma unroll
    for (int t = 0; t < 6; t++) {
        int idx = tid + t * 256;
        int row = idx / 12, seg = idx % 12;
        boff[t] = row * TPITCH + seg * 16;
        soff[t] = (long)row * KSPL + seg * 8;
    }

    const __nv_bfloat16* ksrc = g_ks + (size_t)b * N_ * KSPL;

    // prologue: group0 = VB + K0 ; group1 = K1
    #pragma unroll
    for (int t = 0; t < 4; t++)
        cp_async16(smem + OFF_VB + (tid + t * 256) * 16,
                   g_vbar + (size_t)b * N_ + (tid + t * 256) * 4);
    #pragma unroll
    for (int t = 0; t < 6; t++) cp_async16(smem + OFF_K0 + boff[t], ksrc + soff[t]);
    CP_COMMIT();
    #pragma unroll
    for (int t = 0; t < 6; t++)
        cp_async16(smem + OFF_K1 + boff[t], ksrc + (size_t)128 * KSPL + soff[t]);
    CP_COMMIT();

    // A fragments straight from gmem (mma.m16n8k16 A layout), persistent in regs
    uint32_t A[6][4];
    {
        const __nv_bfloat16* q0 =
            g_qs + ((size_t)b * N_ + n0 + wid * 16 + (lane >> 2)) * KSPL + (lane & 3) * 2;
        #pragma unroll
        for (int s = 0; s < 6; s++) {
            A[s][0] = *(const uint32_t*)(q0 + s * 16);
            A[s][1] = *(const uint32_t*)(q0 + s * 16 + 8 * KSPL);
            A[s][2] = *(const uint32_t*)(q0 + s * 16 + 8);
            A[s][3] = *(const uint32_t*)(q0 + s * 16 + 8 * KSPL + 8);
        }
    }

    float den0 = 0.f, den1 = 0.f, num0 = 0.f, num1 = 0.f;
    const float* vbp = (const float*)(smem + OFF_VB);
    const uint32_t kb_lane = (uint32_t)((lane & 7) * TPITCH + (lane >> 3) * 16);

    for (int ci = 0; ci < NCHUNK; ci++) {
        if (ci == NCHUNK - 1) { CP_WAIT(0); } else { CP_WAIT(1); }
        __syncthreads();

        const uint32_t kbase = sb + ((ci & 1) ? OFF_K1 : OFF_K0) + kb_lane;
        const float* vb = vbp + ci * 128 + (lane & 3) * 2;

        #pragma unroll
        for (int j = 0; j < 16; j++) {
            uint32_t b0, b1, b2, b3, b4, b5, b6, b7, b8, b9, b10, b11;
            uint32_t a = kbase + j * (8 * TPITCH);
            ldsm_x4(b0, b1, b2, b3, a);          // k 0..31
            ldsm_x4(b4, b5, b6, b7, a + 64);     // k 32..63
            ldsm_x4(b8, b9, b10, b11, a + 128);  // k 64..95

            // 3 independent 2-MMA chains
            float p0, p1, p2, p3, q0, q1, q2, q3, r0, r1, r2, r3;
            mma_bf16(p0, p1, p2, p3, A[0][0], A[0][1], A[0][2], A[0][3], b0, b1,
                     0.f, 0.f, 0.f, 0.f);
            mma_bf16(q0, q1, q2, q3, A[2][0], A[2][1], A[2][2], A[2][3], b4, b5,
                     0.f, 0.f, 0.f, 0.f);
            mma_bf16(r0, r1, r2, r3, A[4][0], A[4][1], A[4][2], A[4][3], b8, b9,
                     0.f, 0.f, 0.f, 0.f);
            mma_bf16(p0, p1, p2, p3, A[1][0], A[1][1], A[1][2], A[1][3], b2, b3,
                     p0, p1, p2, p3);
            mma_bf16(q0, q1, q2, q3, A[3][0], A[3][1], A[3][2], A[3][3], b6, b7,
                     q0, q1, q2, q3);
            mma_bf16(r0, r1, r2, r3, A[5][0], A[5][1], A[5][2], A[5][3], b10, b11,
                     r0, r1, r2, r3);

            float d0 = (p0 + q0) + r0;
            float d1 = (p1 + q1) + r1;
            float d2 = (p2 + q2) + r2;
            float d3 = (p3 + q3) + r3;

            // epilogue: cols j*8 + (lane&3)*2 + {0,1}; rows lane/4, lane/4+8
            float2 vv = *(const float2*)(vb + j * 8);
            float e0 = ex2f(d0), e1 = ex2f(d1);
            float e2 = ex2f(d2), e3 = ex2f(d3);
            den0 += e0 + e1;
            num0 = fmaf(e0, vv.x, fmaf(e1, vv.y, num0));
            den1 += e2 + e3;
            num1 = fmaf(e2, vv.x, fmaf(e3, vv.y, num1));
        }

        __syncthreads();
        if (ci + 2 < NCHUNK) {   // refill the buffer chunk ci just finished with
            char* dst = smem + ((ci & 1) ? OFF_K1 : OFF_K0);
            const __nv_bfloat16* src = ksrc + (size_t)(ci + 2) * 128 * KSPL;
            #pragma unroll
            for (int t = 0; t < 6; t++) cp_async16(dst + boff[t], src + soff[t]);
            CP_COMMIT();
        }
    }

    // reduce across the 4 lanes of each quad (they share the same rows)
    #pragma unroll
    for (int off = 1; off < 4; off <<= 1) {
        den0 += __shfl_xor_sync(0xffffffffu, den0, off);
        num0 += __shfl_xor_sync(0xffffffffu, num0, off);
        den1 += __shfl_xor_sync(0xffffffffu, den1, off);
        num1 += __shfl_xor_sync(0xffffffffu, num1, off);
    }
    if ((lane & 3) == 0) {
        const float g = gamma[0];
        int r0 = n0 + wid * 16 + (lane >> 2);
        size_t i0 = (size_t)b * N_ + r0;
        size_t i1 = i0 + 8;
        out[i0] = g * (num0 / den0) + g_xbar[i0];
        out[i1] = g * (num1 / den1) + g_xbar[i1];
    }
}

// ---------------------------------------------------------------------------
extern "C" void kernel_launch(void* const* d_in, const int* in_sizes, int n_in,
                              void* d_out, int out_size) {
    const float* x     = (const float*)d_in[0];
    const float* Wq    = (const float*)d_in[1];
    const float* bq    = (const float*)d_in[2];
    const float* Wk    = (const float*)d_in[3];
    const float* bk    = (const float*)d_in[4];
    const float* Wv    = (const float*)d_in[5];
    const float* bv    = (const float*)d_in[6];
    const float* gamma = (const float*)d_in[7];
    float* out = (float*)d_out;

    prep_kernel<<<1, 256>>>(Wv, bv);
    qk_gemm<<<NROWS / 128, 256>>>(x, Wq, bq, Wk, bk);

    cudaFuncSetAttribute(attn_kernel, cudaFuncAttributeMaxDynamicSharedMemorySize, SMEM_TOT);
    attn_kernel<<<dim3(N_ / 128, B_), 256, SMEM_TOT>>>(gamma, out);
}

// round 6
// speedup vs baseline: 1.2245x; 1.2245x over previous
#include <cuda_runtime.h>
#include <cuda_bf16.h>
#include <math.h>
#include <stdint.h>

#define B_    8
#define N_    4096
#define CIN   256
#define CQK   32
#define NROWS (B_ * N_)   // 32768
#define KSPL  96          // split-K: [hi|lo|hi] x [hi|hi|lo]
#define NCHUNK (N_ / 128) // 32
#define LOG2E 1.4426950408889634f

// ---- scratch (device globals; no allocation allowed) ----
__device__ __nv_bfloat16 g_qs[NROWS * KSPL];   // 6 MB  [row][96], pre-scaled by log2e
__device__ __nv_bfloat16 g_ks[NROWS * KSPL];   // 6 MB  [row][96]
__device__ float g_vbar[NROWS];
__device__ float g_xbar[NROWS];
__device__ float g_wvbar[CIN];
__device__ float g_bvbar;

// =========================== PTX helpers ===================================
__device__ __forceinline__ uint32_t smem_u32(const void* p) {
    uint32_t a;
    asm("{ .reg .u64 t; cvta.to.shared.u64 t, %1; cvt.u32.u64 %0, t; }"
        : "=r"(a) : "l"(p));
    return a;
}
__device__ __forceinline__ void cp_async16(void* dst, const void* src) {
    uint32_t d = smem_u32(dst);
    asm volatile("cp.async.cg.shared.global [%0], [%1], 16;" :: "r"(d), "l"(src) : "memory");
}
#define CP_COMMIT()  asm volatile("cp.async.commit_group;" ::: "memory")
#define CP_WAIT(n)   asm volatile("cp.async.wait_group %0;" :: "n"(n) : "memory")

__device__ __forceinline__ void ldsm_x4(uint32_t& r0, uint32_t& r1,
                                        uint32_t& r2, uint32_t& r3, uint32_t a) {
    asm volatile("ldmatrix.sync.aligned.m8n8.x4.shared.b16 {%0,%1,%2,%3}, [%4];"
        : "=r"(r0), "=r"(r1), "=r"(r2), "=r"(r3) : "r"(a));
}
__device__ __forceinline__ void mma_bf16(float& d0, float& d1, float& d2, float& d3,
    uint32_t a0, uint32_t a1, uint32_t a2, uint32_t a3,
    uint32_t b0, uint32_t b1,
    float c0, float c1, float c2, float c3) {
    asm volatile("mma.sync.aligned.m16n8k16.row.col.f32.bf16.bf16.f32 "
        "{%0,%1,%2,%3},{%4,%5,%6,%7},{%8,%9},{%10,%11,%12,%13};"
        : "=f"(d0), "=f"(d1), "=f"(d2), "=f"(d3)
        : "r"(a0), "r"(a1), "r"(a2), "r"(a3), "r"(b0), "r"(b1),
          "f"(c0), "f"(c1), "f"(c2), "f"(c3));
}
__device__ __forceinline__ float ex2f(float x) {
    float r;
    asm("ex2.approx.f32 %0, %1;" : "=f"(r) : "f"(x));
    return r;
}

// =========================== prep kernel (parallel) ========================
// One warp per Wv row, coalesced lane-strided loads + shfl reduce.
// grid = 32 CTAs x 256 thr (8 warps) -> 256 rows.
__global__ __launch_bounds__(256) void prep_kernel(
    const float* __restrict__ Wv, const float* __restrict__ bv) {
    const int wid = threadIdx.x >> 5, lane = threadIdx.x & 31;
    const int row = blockIdx.x * 8 + wid;
    const float* wr = Wv + (size_t)row * CIN;
    float s = 0.f;
    #pragma unroll
    for (int j = 0; j < 8; j++) s += wr[lane + j * 32];
    #pragma unroll
    for (int off = 16; off > 0; off >>= 1)
        s += __shfl_xor_sync(0xffffffffu, s, off);
    if (lane == 0) g_wvbar[row] = s * (1.f / CIN);

    if (blockIdx.x == 0 && wid == 0) {
        float t = 0.f;
        #pragma unroll
        for (int j = 0; j < 8; j++) t += bv[lane + j * 32];
        #pragma unroll
        for (int off = 16; off > 0; off >>= 1)
            t += __shfl_xor_sync(0xffffffffu, t, off);
        if (lane == 0) g_bvbar = t * (1.f / CIN);
    }
}

// ======================= Q/K projection GEMM (+ fused vbar/xbar) ===========
// C(32768 x 64) = x(32768 x 256) @ [Wq|Wk](256 x 64) + bias.
// Q scaled by log2e, then both split to bf16: g_qs=[hi|lo|hi], g_ks=[hi|hi|lo].
// Also: vbar[row] = x[row,:].wvbar + bvbar, xbar[row] = mean(x[row,:]).
__device__ __forceinline__ uint32_t pack_bf2(float a, float b) {
    __nv_bfloat162 t = __floats2bfloat162_rn(a, b);
    return *reinterpret_cast<uint32_t*>(&t);
}

__global__ __launch_bounds__(256) void qk_gemm(
    const float* __restrict__ x,
    const float* __restrict__ Wq, const float* __restrict__ bq,
    const float* __restrict__ Wk, const float* __restrict__ bk) {

    __shared__ __align__(16) float As[128][36];
    __shared__ __align__(16) float Bs[32][64];
    __shared__ float wv_s[CIN];

    const int tid = threadIdx.x;
    const int tx = tid & 15, ty = tid >> 4;
    const int m0 = blockIdx.x * 128;

    wv_s[tid] = g_wvbar[tid];

    float acc[8][4];
    #pragma unroll
    for (int i = 0; i < 8; i++)
        #pragma unroll
        for (int j = 0; j < 4; j++) acc[i][j] = 0.f;

    float sv = 0.f, sx = 0.f;
    const int srow = tid >> 1, scb = (tid & 1) * 16;

    for (int kt = 0; kt < CIN; kt += 32) {
        {
            int c4 = tid & 7, r0 = tid >> 3;
            #pragma unroll
            for (int p = 0; p < 4; p++) {
                int r = r0 + p * 32;
                *(float4*)(&As[r][c4 * 4]) =
                    *(const float4*)(x + (size_t)(m0 + r) * CIN + kt + c4 * 4);
            }
        }
        {
            int c4 = tid & 15, r0 = tid >> 4;
            #pragma unroll
            for (int p = 0; p < 2; p++) {
                int r = r0 + p * 16;
                float4 v;
                if (c4 < 8) v = *(const float4*)(Wq + (size_t)(kt + r) * CQK + c4 * 4);
                else        v = *(const float4*)(Wk + (size_t)(kt + r) * CQK + (c4 - 8) * 4);
                *(float4*)(&Bs[r][c4 * 4]) = v;
            }
        }
        __syncthreads();

        #pragma unroll
        for (int kk = 0; kk < 32; kk++) {
            float a[8];
            #pragma unroll
            for (int i = 0; i < 8; i++) a[i] = As[ty * 8 + i][kk];
            float4 bv4 = *(const float4*)(&Bs[kk][tx * 4]);
            #pragma unroll
            for (int i = 0; i < 8; i++) {
                acc[i][0] += a[i] * bv4.x;
                acc[i][1] += a[i] * bv4.y;
                acc[i][2] += a[i] * bv4.z;
                acc[i][3] += a[i] * bv4.w;
            }
        }

        // fused row-sum pass over the As tile (vbar / xbar)
        #pragma unroll
        for (int j = 0; j < 16; j++) {
            float xv = As[srow][scb + j];
            sx += xv;
            sv = fmaf(wv_s[kt + scb + j], xv, sv);
        }
        __syncthreads();
    }

    // vbar / xbar writeback (threads paired on bit 0)
    sv += __shfl_xor_sync(0xffffffffu, sv, 1);
    sx += __shfl_xor_sync(0xffffffffu, sx, 1);
    if ((tid & 1) == 0) {
        g_vbar[m0 + srow] = sv + g_bvbar;
        g_xbar[m0 + srow] = sx * (1.f / CIN);
    }

    const int c = tx * 4;
    const bool isQ = (c < 32);
    const int c0 = isQ ? c : c - 32;
    float4 bb = isQ ? *(const float4*)(bq + c0) : *(const float4*)(bk + c0);
    const float scale = isQ ? LOG2E : 1.f;

    #pragma unroll
    for (int i = 0; i < 8; i++) {
        size_t row = (size_t)m0 + ty * 8 + i;
        float v0 = (acc[i][0] + bb.x) * scale, v1 = (acc[i][1] + bb.y) * scale;
        float v2 = (acc[i][2] + bb.z) * scale, v3 = (acc[i][3] + bb.w) * scale;
        __nv_bfloat16 h0 = __float2bfloat16_rn(v0), h1 = __float2bfloat16_rn(v1);
        __nv_bfloat16 h2 = __float2bfloat16_rn(v2), h3 = __float2bfloat16_rn(v3);
        float l0 = v0 - __bfloat162float(h0), l1 = v1 - __bfloat162float(h1);
        float l2 = v2 - __bfloat162float(h2), l3 = v3 - __bfloat162float(h3);
        uint2 hi = make_uint2(pack_bf2(v0, v1), pack_bf2(v2, v3));
        uint2 lo = make_uint2(pack_bf2(l0, l1), pack_bf2(l2, l3));
        if (isQ) {
            __nv_bfloat16* dst = g_qs + row * KSPL + c0;
            *(uint2*)(dst)      = hi;   // q_hi
            *(uint2*)(dst + 32) = lo;   // q_lo
            *(uint2*)(dst + 64) = hi;   // q_hi
        } else {
            __nv_bfloat16* dst = g_ks + row * KSPL + c0;
            *(uint2*)(dst)      = hi;   // k_hi
            *(uint2*)(dst + 32) = hi;   // k_hi
            *(uint2*)(dst + 64) = lo;   // k_lo
        }
    }
}

// =========================== attention kernel ==============================
// smem K tiles: [128 rows][104 bf16] (208-B pitch -> conflict-free ldmatrix)
#define TPITCH   208
#define TILE_B   (128 * TPITCH)      // 26624
#define OFF_VB   0                   // 16 KB vbar
#define OFF_K0   16384
#define OFF_K1   (OFF_K0 + TILE_B)   // 43008
#define SMEM_TOT (OFF_K1 + TILE_B)   // 69632

__global__ __launch_bounds__(256, 2) void attn_kernel(
    const float* __restrict__ gamma, float* __restrict__ out) {

    extern __shared__ __align__(16) char smem[];
    const uint32_t sb = smem_u32(smem);
    const int tid = threadIdx.x, wid = tid >> 5, lane = tid & 31;
    const int b = blockIdx.y, n0 = blockIdx.x * 128;

    // per-thread cp.async offsets for a 128x96 bf16 tile (1536 16B segs, 6/thread)
    int boff[6]; long soff[6];
    #pragma unroll
    for (int t = 0; t < 6; t++) {
        int idx = tid + t * 256;
        int row = idx / 12, seg = idx % 12;
        boff[t] = row * TPITCH + seg * 16;
        soff[t] = (long)row * KSPL + seg * 8;
    }

    const __nv_bfloat16* ksrc = g_ks + (size_t)b * N_ * KSPL;

    // prologue: group0 = VB + K0 ; group1 = K1
    #pragma unroll
    for (int t = 0; t < 4; t++)
        cp_async16(smem + OFF_VB + (tid + t * 256) * 16,
                   g_vbar + (size_t)b * N_ + (tid + t * 256) * 4);
    #pragma unroll
    for (int t = 0; t < 6; t++) cp_async16(smem + OFF_K0 + boff[t], ksrc + soff[t]);
    CP_COMMIT();
    #pragma unroll
    for (int t = 0; t < 6; t++)
        cp_async16(smem + OFF_K1 + boff[t], ksrc + (size_t)128 * KSPL + soff[t]);
    CP_COMMIT();

    // A fragments straight from gmem (mma.m16n8k16 A layout), persistent in regs
    uint32_t A[6][4];
    {
        const __nv_bfloat16* q0 =
            g_qs + ((size_t)b * N_ + n0 + wid * 16 + (lane >> 2)) * KSPL + (lane & 3) * 2;
        #pragma unroll
        for (int s = 0; s < 6; s++) {
            A[s][0] = *(const uint32_t*)(q0 + s * 16);
            A[s][1] = *(const uint32_t*)(q0 + s * 16 + 8 * KSPL);
            A[s][2] = *(const uint32_t*)(q0 + s * 16 + 8);
            A[s][3] = *(const uint32_t*)(q0 + s * 16 + 8 * KSPL + 8);
        }
    }

    float den0 = 0.f, den1 = 0.f, num0 = 0.f, num1 = 0.f;
    const float* vbp = (const float*)(smem + OFF_VB);
    const uint32_t kb_lane = (uint32_t)((lane & 7) * TPITCH + (lane >> 3) * 16);

    for (int ci = 0; ci < NCHUNK; ci++) {
        if (ci == NCHUNK - 1) { CP_WAIT(0); } else { CP_WAIT(1); }
        __syncthreads();

        const uint32_t kbase = sb + ((ci & 1) ? OFF_K1 : OFF_K0) + kb_lane;
        const float* vb = vbp + ci * 128 + (lane & 3) * 2;

        #pragma unroll
        for (int j = 0; j < 16; j++) {
            uint32_t b0, b1, b2, b3, b4, b5, b6, b7, b8, b9, b10, b11;
            uint32_t a = kbase + j * (8 * TPITCH);
            ldsm_x4(b0, b1, b2, b3, a);          // k 0..31
            ldsm_x4(b4, b5, b6, b7, a + 64);     // k 32..63
            ldsm_x4(b8, b9, b10, b11, a + 128);  // k 64..95

            // 3 independent 2-MMA chains
            float p0, p1, p2, p3, q0, q1, q2, q3, r0, r1, r2, r3;
            mma_bf16(p0, p1, p2, p3, A[0][0], A[0][1], A[0][2], A[0][3], b0, b1,
                     0.f, 0.f, 0.f, 0.f);
            mma_bf16(q0, q1, q2, q3, A[2][0], A[2][1], A[2][2], A[2][3], b4, b5,
                     0.f, 0.f, 0.f, 0.f);
            mma_bf16(r0, r1, r2, r3, A[4][0], A[4][1], A[4][2], A[4][3], b8, b9,
                     0.f, 0.f, 0.f, 0.f);
            mma_bf16(p0, p1, p2, p3, A[1][0], A[1][1], A[1][2], A[1][3], b2, b3,
                     p0, p1, p2, p3);
            mma_bf16(q0, q1, q2, q3, A[3][0], A[3][1], A[3][2], A[3][3], b6, b7,
                     q0, q1, q2, q3);
            mma_bf16(r0, r1, r2, r3, A[5][0], A[5][1], A[5][2], A[5][3], b10, b11,
                     r0, r1, r2, r3);

            float d0 = (p0 + q0) + r0;
            float d1 = (p1 + q1) + r1;
            float d2 = (p2 + q2) + r2;
            float d3 = (p3 + q3) + r3;

            // epilogue: cols j*8 + (lane&3)*2 + {0,1}; rows lane/4, lane/4+8
            float2 vv = *(const float2*)(vb + j * 8);
            float e0 = ex2f(d0), e1 = ex2f(d1);
            float e2 = ex2f(d2), e3 = ex2f(d3);
            den0 += e0 + e1;
            num0 = fmaf(e0, vv.x, fmaf(e1, vv.y, num0));
            den1 += e2 + e3;
            num1 = fmaf(e2, vv.x, fmaf(e3, vv.y, num1));
        }

        __syncthreads();
        if (ci + 2 < NCHUNK) {   // refill the buffer chunk ci just finished with
            char* dst = smem + ((ci & 1) ? OFF_K1 : OFF_K0);
            const __nv_bfloat16* src = ksrc + (size_t)(ci + 2) * 128 * KSPL;
            #pragma unroll
            for (int t = 0; t < 6; t++) cp_async16(dst + boff[t], src + soff[t]);
            CP_COMMIT();
        }
    }

    // reduce across the 4 lanes of each quad (they share the same rows)
    #pragma unroll
    for (int off = 1; off < 4; off <<= 1) {
        den0 += __shfl_xor_sync(0xffffffffu, den0, off);
        num0 += __shfl_xor_sync(0xffffffffu, num0, off);
        den1 += __shfl_xor_sync(0xffffffffu, den1, off);
        num1 += __shfl_xor_sync(0xffffffffu, num1, off);
    }
    if ((lane & 3) == 0) {
        const float g = gamma[0];
        int r0 = n0 + wid * 16 + (lane >> 2);
        size_t i0 = (size_t)b * N_ + r0;
        size_t i1 = i0 + 8;
        out[i0] = g * (num0 / den0) + g_xbar[i0];
        out[i1] = g * (num1 / den1) + g_xbar[i1];
    }
}

// ---------------------------------------------------------------------------
extern "C" void kernel_launch(void* const* d_in, const int* in_sizes, int n_in,
                              void* d_out, int out_size) {
    const float* x     = (const float*)d_in[0];
    const float* Wq    = (const float*)d_in[1];
    const float* bq    = (const float*)d_in[2];
    const float* Wk    = (const float*)d_in[3];
    const float* bk    = (const float*)d_in[4];
    const float* Wv    = (const float*)d_in[5];
    const float* bv    = (const float*)d_in[6];
    const float* gamma = (const float*)d_in[7];
    float* out = (float*)d_out;

    prep_kernel<<<32, 256>>>(Wv, bv);
    qk_gemm<<<NROWS / 128, 256>>>(x, Wq, bq, Wk, bk);

    cudaFuncSetAttribute(attn_kernel, cudaFuncAttributeMaxDynamicSharedMemorySize, SMEM_TOT);
    attn_kernel<<<dim3(N_ / 128, B_), 256, SMEM_TOT>>>(gamma, out);
}

// round 7
// speedup vs baseline: 1.3945x; 1.1388x over previous
#include <cuda_runtime.h>
#include <cuda_bf16.h>
#include <math.h>
#include <stdint.h>

#define B_    8
#define N_    4096
#define CIN   256
#define CQK   32
#define NROWS (B_ * N_)   // 32768
#define KSPL  96          // split-K: [hi|lo|hi] x [hi|hi|lo]
#define NCHUNK (N_ / 128) // 32
#define LOG2E 1.4426950408889634f

// ---- scratch (device globals; no allocation allowed) ----
__device__ __nv_bfloat16 g_qs[NROWS * KSPL];   // 6 MB  [row][96], pre-scaled by log2e
__device__ __nv_bfloat16 g_ks[NROWS * KSPL];   // 6 MB  [row][96]
__device__ __nv_bfloat16 g_vbh[NROWS];         // vbar hi (bf16)
__device__ __nv_bfloat16 g_vbl[NROWS];         // vbar lo (bf16 residual)
__device__ float g_xbar[NROWS];
__device__ float g_wvbar[CIN];
__device__ float g_bvbar;

// =========================== PTX helpers ===================================
__device__ __forceinline__ uint32_t smem_u32(const void* p) {
    uint32_t a;
    asm("{ .reg .u64 t; cvta.to.shared.u64 t, %1; cvt.u32.u64 %0, t; }"
        : "=r"(a) : "l"(p));
    return a;
}
__device__ __forceinline__ void cp_async16(void* dst, const void* src) {
    uint32_t d = smem_u32(dst);
    asm volatile("cp.async.cg.shared.global [%0], [%1], 16;" :: "r"(d), "l"(src) : "memory");
}
#define CP_COMMIT()  asm volatile("cp.async.commit_group;" ::: "memory")
#define CP_WAIT(n)   asm volatile("cp.async.wait_group %0;" :: "n"(n) : "memory")

__device__ __forceinline__ void ldsm_x4(uint32_t& r0, uint32_t& r1,
                                        uint32_t& r2, uint32_t& r3, uint32_t a) {
    asm volatile("ldmatrix.sync.aligned.m8n8.x4.shared.b16 {%0,%1,%2,%3}, [%4];"
        : "=r"(r0), "=r"(r1), "=r"(r2), "=r"(r3) : "r"(a));
}
__device__ __forceinline__ void mma_bf16(float& d0, float& d1, float& d2, float& d3,
    uint32_t a0, uint32_t a1, uint32_t a2, uint32_t a3,
    uint32_t b0, uint32_t b1,
    float c0, float c1, float c2, float c3) {
    asm volatile("mma.sync.aligned.m16n8k16.row.col.f32.bf16.bf16.f32 "
        "{%0,%1,%2,%3},{%4,%5,%6,%7},{%8,%9},{%10,%11,%12,%13};"
        : "=f"(d0), "=f"(d1), "=f"(d2), "=f"(d3)
        : "r"(a0), "r"(a1), "r"(a2), "r"(a3), "r"(b0), "r"(b1),
          "f"(c0), "f"(c1), "f"(c2), "f"(c3));
}
__device__ __forceinline__ float ex2f(float x) {
    float r;
    asm("ex2.approx.f32 %0, %1;" : "=f"(r) : "f"(x));
    return r;
}
// pack two f32 into bf16x2: low half = lo, high half = hi
__device__ __forceinline__ uint32_t cvt_bf2(float hi, float lo) {
    uint32_t r;
    asm("cvt.rn.bf16x2.f32 %0, %1, %2;" : "=r"(r) : "f"(hi), "f"(lo));
    return r;
}

// =========================== prep kernel (parallel) ========================
__global__ __launch_bounds__(256) void prep_kernel(
    const float* __restrict__ Wv, const float* __restrict__ bv) {
    const int wid = threadIdx.x >> 5, lane = threadIdx.x & 31;
    const int row = blockIdx.x * 8 + wid;
    const float* wr = Wv + (size_t)row * CIN;
    float s = 0.f;
    #pragma unroll
    for (int j = 0; j < 8; j++) s += wr[lane + j * 32];
    #pragma unroll
    for (int off = 16; off > 0; off >>= 1)
        s += __shfl_xor_sync(0xffffffffu, s, off);
    if (lane == 0) g_wvbar[row] = s * (1.f / CIN);

    if (blockIdx.x == 0 && wid == 0) {
        float t = 0.f;
        #pragma unroll
        for (int j = 0; j < 8; j++) t += bv[lane + j * 32];
        #pragma unroll
        for (int off = 16; off > 0; off >>= 1)
            t += __shfl_xor_sync(0xffffffffu, t, off);
        if (lane == 0) g_bvbar = t * (1.f / CIN);
    }
}

// ======================= Q/K projection GEMM (+ fused vbar/xbar) ===========
__device__ __forceinline__ uint32_t pack_bf2(float a, float b) {
    __nv_bfloat162 t = __floats2bfloat162_rn(a, b);
    return *reinterpret_cast<uint32_t*>(&t);
}

__global__ __launch_bounds__(256) void qk_gemm(
    const float* __restrict__ x,
    const float* __restrict__ Wq, const float* __restrict__ bq,
    const float* __restrict__ Wk, const float* __restrict__ bk) {

    __shared__ __align__(16) float As[128][36];
    __shared__ __align__(16) float Bs[32][64];
    __shared__ float wv_s[CIN];

    const int tid = threadIdx.x;
    const int tx = tid & 15, ty = tid >> 4;
    const int m0 = blockIdx.x * 128;

    wv_s[tid] = g_wvbar[tid];

    float acc[8][4];
    #pragma unroll
    for (int i = 0; i < 8; i++)
        #pragma unroll
        for (int j = 0; j < 4; j++) acc[i][j] = 0.f;

    float sv = 0.f, sx = 0.f;
    const int srow = tid >> 1, scb = (tid & 1) * 16;

    for (int kt = 0; kt < CIN; kt += 32) {
        {
            int c4 = tid & 7, r0 = tid >> 3;
            #pragma unroll
            for (int p = 0; p < 4; p++) {
                int r = r0 + p * 32;
                *(float4*)(&As[r][c4 * 4]) =
                    *(const float4*)(x + (size_t)(m0 + r) * CIN + kt + c4 * 4);
            }
        }
        {
            int c4 = tid & 15, r0 = tid >> 4;
            #pragma unroll
            for (int p = 0; p < 2; p++) {
                int r = r0 + p * 16;
                float4 v;
                if (c4 < 8) v = *(const float4*)(Wq + (size_t)(kt + r) * CQK + c4 * 4);
                else        v = *(const float4*)(Wk + (size_t)(kt + r) * CQK + (c4 - 8) * 4);
                *(float4*)(&Bs[r][c4 * 4]) = v;
            }
        }
        __syncthreads();

        #pragma unroll
        for (int kk = 0; kk < 32; kk++) {
            float a[8];
            #pragma unroll
            for (int i = 0; i < 8; i++) a[i] = As[ty * 8 + i][kk];
            float4 bv4 = *(const float4*)(&Bs[kk][tx * 4]);
            #pragma unroll
            for (int i = 0; i < 8; i++) {
                acc[i][0] += a[i] * bv4.x;
                acc[i][1] += a[i] * bv4.y;
                acc[i][2] += a[i] * bv4.z;
                acc[i][3] += a[i] * bv4.w;
            }
        }

        // fused row-sum pass over the As tile (vbar / xbar)
        #pragma unroll
        for (int j = 0; j < 16; j++) {
            float xv = As[srow][scb + j];
            sx += xv;
            sv = fmaf(wv_s[kt + scb + j], xv, sv);
        }
        __syncthreads();
    }

    // vbar / xbar writeback (threads paired on bit 0); vbar hi/lo bf16 split
    sv += __shfl_xor_sync(0xffffffffu, sv, 1);
    sx += __shfl_xor_sync(0xffffffffu, sx, 1);
    if ((tid & 1) == 0) {
        float vb = sv + g_bvbar;
        __nv_bfloat16 h = __float2bfloat16_rn(vb);
        g_vbh[m0 + srow] = h;
        g_vbl[m0 + srow] = __float2bfloat16_rn(vb - __bfloat162float(h));
        g_xbar[m0 + srow] = sx * (1.f / CIN);
    }

    const int c = tx * 4;
    const bool isQ = (c < 32);
    const int c0 = isQ ? c : c - 32;
    float4 bb = isQ ? *(const float4*)(bq + c0) : *(const float4*)(bk + c0);
    const float scale = isQ ? LOG2E : 1.f;

    #pragma unroll
    for (int i = 0; i < 8; i++) {
        size_t row = (size_t)m0 + ty * 8 + i;
        float v0 = (acc[i][0] + bb.x) * scale, v1 = (acc[i][1] + bb.y) * scale;
        float v2 = (acc[i][2] + bb.z) * scale, v3 = (acc[i][3] + bb.w) * scale;
        __nv_bfloat16 h0 = __float2bfloat16_rn(v0), h1 = __float2bfloat16_rn(v1);
        __nv_bfloat16 h2 = __float2bfloat16_rn(v2), h3 = __float2bfloat16_rn(v3);
        float l0 = v0 - __bfloat162float(h0), l1 = v1 - __bfloat162float(h1);
        float l2 = v2 - __bfloat162float(h2), l3 = v3 - __bfloat162float(h3);
        uint2 hi = make_uint2(pack_bf2(v0, v1), pack_bf2(v2, v3));
        uint2 lo = make_uint2(pack_bf2(l0, l1), pack_bf2(l2, l3));
        if (isQ) {
            __nv_bfloat16* dst = g_qs + row * KSPL + c0;
            *(uint2*)(dst)      = hi;   // q_hi
            *(uint2*)(dst + 32) = lo;   // q_lo
            *(uint2*)(dst + 64) = hi;   // q_hi
        } else {
            __nv_bfloat16* dst = g_ks + row * KSPL + c0;
            *(uint2*)(dst)      = hi;   // k_hi
            *(uint2*)(dst + 32) = hi;   // k_hi
            *(uint2*)(dst + 64) = lo;   // k_lo
        }
    }
}

// =========================== attention kernel ==============================
// smem: vb_hi (8K) + vb_lo (8K) + two K tiles [128][104 bf16] (208-B pitch)
#define TPITCH   208
#define TILE_B   (128 * TPITCH)      // 26624
#define OFF_VH   0
#define OFF_VL   8192
#define OFF_K0   16384
#define OFF_K1   (OFF_K0 + TILE_B)   // 43008
#define SMEM_TOT (OFF_K1 + TILE_B)   // 69632

__global__ __launch_bounds__(256, 2) void attn_kernel(
    const float* __restrict__ gamma, float* __restrict__ out) {

    extern __shared__ __align__(16) char smem[];
    const uint32_t sb = smem_u32(smem);
    const int tid = threadIdx.x, wid = tid >> 5, lane = tid & 31;
    const int b = blockIdx.y, n0 = blockIdx.x * 128;

    // per-thread cp.async offsets for a 128x96 bf16 tile (1536 16B segs, 6/thread)
    int boff[6]; long soff[6];
    #pragma unroll
    for (int t = 0; t < 6; t++) {
        int idx = tid + t * 256;
        int row = idx / 12, seg = idx % 12;
        boff[t] = row * TPITCH + seg * 16;
        soff[t] = (long)row * KSPL + seg * 8;
    }

    const __nv_bfloat16* ksrc = g_ks + (size_t)b * N_ * KSPL;

    // prologue: group0 = VH + VL + K0 ; group1 = K1
    #pragma unroll
    for (int t = 0; t < 2; t++) {
        cp_async16(smem + OFF_VH + (tid + t * 256) * 16,
                   g_vbh + (size_t)b * N_ + (tid + t * 256) * 8);
        cp_async16(smem + OFF_VL + (tid + t * 256) * 16,
                   g_vbl + (size_t)b * N_ + (tid + t * 256) * 8);
    }
    #pragma unroll
    for (int t = 0; t < 6; t++) cp_async16(smem + OFF_K0 + boff[t], ksrc + soff[t]);
    CP_COMMIT();
    #pragma unroll
    for (int t = 0; t < 6; t++)
        cp_async16(smem + OFF_K1 + boff[t], ksrc + (size_t)128 * KSPL + soff[t]);
    CP_COMMIT();

    // A fragments straight from gmem (mma.m16n8k16 A layout), persistent in regs
    uint32_t A[6][4];
    {
        const __nv_bfloat16* q0 =
            g_qs + ((size_t)b * N_ + n0 + wid * 16 + (lane >> 2)) * KSPL + (lane & 3) * 2;
        #pragma unroll
        for (int s = 0; s < 6; s++) {
            A[s][0] = *(const uint32_t*)(q0 + s * 16);
            A[s][1] = *(const uint32_t*)(q0 + s * 16 + 8 * KSPL);
            A[s][2] = *(const uint32_t*)(q0 + s * 16 + 8);
            A[s][3] = *(const uint32_t*)(q0 + s * 16 + 8 * KSPL + 8);
        }
    }

    // PV accumulator: C[r][n]: n0/1 = num(hi/lo parts), n2 = den (ones column)
    float c0 = 0.f, c1 = 0.f, c2 = 0.f, c3 = 0.f;

    const int nn = lane >> 2;      // PV B column owned by this lane
    const __nv_bfloat16* vbase =
        (nn == 0) ? (const __nv_bfloat16*)(smem + OFF_VH)
                  : (const __nv_bfloat16*)(smem + OFF_VL);
    const uint32_t bconst = (nn == 2) ? 0x3F803F80u : 0u;   // bf16x2 (1,1) or 0

    const uint32_t kb_lane = (uint32_t)((lane & 7) * TPITCH + (lane >> 3) * 16);

    for (int ci = 0; ci < NCHUNK; ci++) {
        if (ci == NCHUNK - 1) { CP_WAIT(0); } else { CP_WAIT(1); }
        __syncthreads();

        const uint32_t kbase = sb + ((ci & 1) ? OFF_K1 : OFF_K0) + kb_lane;
        const __nv_bfloat16* vc = vbase + ci * 128 + (lane & 3) * 2;

        #pragma unroll
        for (int s = 0; s < 8; s++) {
            // ---- QK for j = 2s and j = 2s+1 (serial 6-MMA chains) ----
            float da0, da1, da2, da3, db0, db1, db2, db3;
            {
                uint32_t r0, r1, r2, r3, r4, r5, r6, r7, r8, r9, r10, r11;
                uint32_t a = kbase + (2 * s) * (8 * TPITCH);
                ldsm_x4(r0, r1, r2, r3, a);
                ldsm_x4(r4, r5, r6, r7, a + 64);
                ldsm_x4(r8, r9, r10, r11, a + 128);
                mma_bf16(da0, da1, da2, da3, A[0][0], A[0][1], A[0][2], A[0][3], r0, r1,
                         0.f, 0.f, 0.f, 0.f);
                mma_bf16(da0, da1, da2, da3, A[1][0], A[1][1], A[1][2], A[1][3], r2, r3,
                         da0, da1, da2, da3);
                mma_bf16(da0, da1, da2, da3, A[2][0], A[2][1], A[2][2], A[2][3], r4, r5,
                         da0, da1, da2, da3);
                mma_bf16(da0, da1, da2, da3, A[3][0], A[3][1], A[3][2], A[3][3], r6, r7,
                         da0, da1, da2, da3);
                mma_bf16(da0, da1, da2, da3, A[4][0], A[4][1], A[4][2], A[4][3], r8, r9,
                         da0, da1, da2, da3);
                mma_bf16(da0, da1, da2, da3, A[5][0], A[5][1], A[5][2], A[5][3], r10, r11,
                         da0, da1, da2, da3);
            }
            {
                uint32_t r0, r1, r2, r3, r4, r5, r6, r7, r8, r9, r10, r11;
                uint32_t a = kbase + (2 * s + 1) * (8 * TPITCH);
                ldsm_x4(r0, r1, r2, r3, a);
                ldsm_x4(r4, r5, r6, r7, a + 64);
                ldsm_x4(r8, r9, r10, r11, a + 128);
                mma_bf16(db0, db1, db2, db3, A[0][0], A[0][1], A[0][2], A[0][3], r0, r1,
                         0.f, 0.f, 0.f, 0.f);
                mma_bf16(db0, db1, db2, db3, A[1][0], A[1][1], A[1][2], A[1][3], r2, r3,
                         db0, db1, db2, db3);
                mma_bf16(db0, db1, db2, db3, A[2][0], A[2][1], A[2][2], A[2][3], r4, r5,
                         db0, db1, db2, db3);
                mma_bf16(db0, db1, db2, db3, A[3][0], A[3][1], A[3][2], A[3][3], r6, r7,
                         db0, db1, db2, db3);
                mma_bf16(db0, db1, db2, db3, A[4][0], A[4][1], A[4][2], A[4][3], r8, r9,
                         db0, db1, db2, db3);
                mma_bf16(db0, db1, db2, db3, A[5][0], A[5][1], A[5][2], A[5][3], r10, r11,
                         db0, db1, db2, db3);
            }

            // ---- softmax numerators as bf16 P fragments ----
            uint32_t a0 = cvt_bf2(ex2f(da1), ex2f(da0));   // row r,   keys 16s+2(l&3)+{0,1}
            uint32_t a1 = cvt_bf2(ex2f(da3), ex2f(da2));   // row r+8
            uint32_t a2 = cvt_bf2(ex2f(db1), ex2f(db0));   // row r,   keys +8
            uint32_t a3 = cvt_bf2(ex2f(db3), ex2f(db2));   // row r+8

            // ---- PV B fragment: cols [vb_hi | vb_lo | 1 | 0...] ----
            uint32_t pb0, pb1;
            if (nn < 2) {
                pb0 = *(const uint32_t*)(vc + 16 * s);
                pb1 = *(const uint32_t*)(vc + 16 * s + 8);
            } else {
                pb0 = bconst; pb1 = bconst;
            }

            mma_bf16(c0, c1, c2, c3, a0, a1, a2, a3, pb0, pb1, c0, c1, c2, c3);
        }

        __syncthreads();
        if (ci + 2 < NCHUNK) {   // refill the buffer chunk ci just finished with
            char* dst = smem + ((ci & 1) ? OFF_K1 : OFF_K0);
            const __nv_bfloat16* src = ksrc + (size_t)(ci + 2) * 128 * KSPL;
            #pragma unroll
            for (int t = 0; t < 6; t++) cp_async16(dst + boff[t], src + soff[t]);
            CP_COMMIT();
        }
    }

    // extraction: lane&3==0 holds num parts (cols 0,1); lane&3==1 holds den (col 2)
    const int base = lane & ~3;
    float den0 = __shfl_sync(0xffffffffu, c0, base + 1);
    float den1 = __shfl_sync(0xffffffffu, c2, base + 1);
    if ((lane & 3) == 0) {
        const float g = gamma[0];
        float num0 = c0 + c1;
        float num1 = c2 + c3;
        int r0 = n0 + wid * 16 + (lane >> 2);
        size_t i0 = (size_t)b * N_ + r0;
        size_t i1 = i0 + 8;
        out[i0] = g * (num0 / den0) + g_xbar[i0];
        out[i1] = g * (num1 / den1) + g_xbar[i1];
    }
}

// ---------------------------------------------------------------------------
extern "C" void kernel_launch(void* const* d_in, const int* in_sizes, int n_in,
                              void* d_out, int out_size) {
    const float* x     = (const float*)d_in[0];
    const float* Wq    = (const float*)d_in[1];
    const float* bq    = (const float*)d_in[2];
    const float* Wk    = (const float*)d_in[3];
    const float* bk    = (const float*)d_in[4];
    const float* Wv    = (const float*)d_in[5];
    const float* bv    = (const float*)d_in[6];
    const float* gamma = (const float*)d_in[7];
    float* out = (float*)d_out;

    prep_kernel<<<32, 256>>>(Wv, bv);
    qk_gemm<<<NROWS / 128, 256>>>(x, Wq, bq, Wk, bk);

    cudaFuncSetAttribute(attn_kernel, cudaFuncAttributeMaxDynamicSharedMemorySize, SMEM_TOT);
    attn_kernel<<<dim3(N_ / 128, B_), 256, SMEM_TOT>>>(gamma, out);
}

// round 8
// speedup vs baseline: 1.9553x; 1.4021x over previous
#include <cuda_runtime.h>
#include <cuda_bf16.h>
#include <cuda_fp16.h>
#include <math.h>
#include <stdint.h>

#define B_    8
#define N_    4096
#define CIN   256
#define CQK   32
#define NROWS (B_ * N_)   // 32768
#define QW    64          // q store: [q_hi(32) | q_lo(32)] fp16
#define KW    32          // k store: k_hi fp16
#define NCHUNK (N_ / 128) // 32
#define LOG2E 1.4426950408889634f

// ---- scratch (device globals; no allocation allowed) ----
__device__ __half g_qs[NROWS * QW];   // 4 MB, pre-scaled by log2e
__device__ __half g_ks[NROWS * KW];   // 2 MB
__device__ __nv_bfloat16 g_vbh[NROWS];
__device__ __nv_bfloat16 g_vbl[NROWS];
__device__ float g_xbar[NROWS];
__device__ float g_wvbar[CIN];
__device__ float g_bvbar;

// =========================== PTX helpers ===================================
__device__ __forceinline__ uint32_t smem_u32(const void* p) {
    uint32_t a;
    asm("{ .reg .u64 t; cvta.to.shared.u64 t, %1; cvt.u32.u64 %0, t; }"
        : "=r"(a) : "l"(p));
    return a;
}
__device__ __forceinline__ void cp_async16(void* dst, const void* src) {
    uint32_t d = smem_u32(dst);
    asm volatile("cp.async.cg.shared.global [%0], [%1], 16;" :: "r"(d), "l"(src) : "memory");
}
#define CP_COMMIT()  asm volatile("cp.async.commit_group;" ::: "memory")
#define CP_WAIT(n)   asm volatile("cp.async.wait_group %0;" :: "n"(n) : "memory")

__device__ __forceinline__ void ldsm_x4(uint32_t& r0, uint32_t& r1,
                                        uint32_t& r2, uint32_t& r3, uint32_t a) {
    asm volatile("ldmatrix.sync.aligned.m8n8.x4.shared.b16 {%0,%1,%2,%3}, [%4];"
        : "=r"(r0), "=r"(r1), "=r"(r2), "=r"(r3) : "r"(a));
}
__device__ __forceinline__ void mma_f16(float& d0, float& d1, float& d2, float& d3,
    uint32_t a0, uint32_t a1, uint32_t a2, uint32_t a3,
    uint32_t b0, uint32_t b1,
    float c0, float c1, float c2, float c3) {
    asm volatile("mma.sync.aligned.m16n8k16.row.col.f32.f16.f16.f32 "
        "{%0,%1,%2,%3},{%4,%5,%6,%7},{%8,%9},{%10,%11,%12,%13};"
        : "=f"(d0), "=f"(d1), "=f"(d2), "=f"(d3)
        : "r"(a0), "r"(a1), "r"(a2), "r"(a3), "r"(b0), "r"(b1),
          "f"(c0), "f"(c1), "f"(c2), "f"(c3));
}
__device__ __forceinline__ void mma_bf16(float& d0, float& d1, float& d2, float& d3,
    uint32_t a0, uint32_t a1, uint32_t a2, uint32_t a3,
    uint32_t b0, uint32_t b1,
    float c0, float c1, float c2, float c3) {
    asm volatile("mma.sync.aligned.m16n8k16.row.col.f32.bf16.bf16.f32 "
        "{%0,%1,%2,%3},{%4,%5,%6,%7},{%8,%9},{%10,%11,%12,%13};"
        : "=f"(d0), "=f"(d1), "=f"(d2), "=f"(d3)
        : "r"(a0), "r"(a1), "r"(a2), "r"(a3), "r"(b0), "r"(b1),
          "f"(c0), "f"(c1), "f"(c2), "f"(c3));
}
__device__ __forceinline__ float ex2f(float x) {
    float r;
    asm("ex2.approx.f32 %0, %1;" : "=f"(r) : "f"(x));
    return r;
}
__device__ __forceinline__ uint32_t cvt_bf2(float hi, float lo) {
    uint32_t r;
    asm("cvt.rn.bf16x2.f32 %0, %1, %2;" : "=r"(r) : "f"(hi), "f"(lo));
    return r;
}

// =========================== prep kernel (parallel) ========================
__global__ __launch_bounds__(256) void prep_kernel(
    const float* __restrict__ Wv, const float* __restrict__ bv) {
    const int wid = threadIdx.x >> 5, lane = threadIdx.x & 31;
    const int row = blockIdx.x * 8 + wid;
    const float* wr = Wv + (size_t)row * CIN;
    float s = 0.f;
    #pragma unroll
    for (int j = 0; j < 8; j++) s += wr[lane + j * 32];
    #pragma unroll
    for (int off = 16; off > 0; off >>= 1)
        s += __shfl_xor_sync(0xffffffffu, s, off);
    if (lane == 0) g_wvbar[row] = s * (1.f / CIN);

    if (blockIdx.x == 0 && wid == 0) {
        float t = 0.f;
        #pragma unroll
        for (int j = 0; j < 8; j++) t += bv[lane + j * 32];
        #pragma unroll
        for (int off = 16; off > 0; off >>= 1)
            t += __shfl_xor_sync(0xffffffffu, t, off);
        if (lane == 0) g_bvbar = t * (1.f / CIN);
    }
}

// ======================= Q/K projection GEMM (+ fused vbar/xbar) ===========
__device__ __forceinline__ uint32_t pack_h2(float a, float b) {
    __half2 t = __floats2half2_rn(a, b);
    return *reinterpret_cast<uint32_t*>(&t);
}

__global__ __launch_bounds__(256) void qk_gemm(
    const float* __restrict__ x,
    const float* __restrict__ Wq, const float* __restrict__ bq,
    const float* __restrict__ Wk, const float* __restrict__ bk) {

    __shared__ __align__(16) float As[128][36];
    __shared__ __align__(16) float Bs[32][64];
    __shared__ float wv_s[CIN];

    const int tid = threadIdx.x;
    const int tx = tid & 15, ty = tid >> 4;
    const int m0 = blockIdx.x * 128;

    wv_s[tid] = g_wvbar[tid];

    float acc[8][4];
    #pragma unroll
    for (int i = 0; i < 8; i++)
        #pragma unroll
        for (int j = 0; j < 4; j++) acc[i][j] = 0.f;

    float sv = 0.f, sx = 0.f;
    const int srow = tid >> 1, scb = (tid & 1) * 16;

    for (int kt = 0; kt < CIN; kt += 32) {
        {
            int c4 = tid & 7, r0 = tid >> 3;
            #pragma unroll
            for (int p = 0; p < 4; p++) {
                int r = r0 + p * 32;
                *(float4*)(&As[r][c4 * 4]) =
                    *(const float4*)(x + (size_t)(m0 + r) * CIN + kt + c4 * 4);
            }
        }
        {
            int c4 = tid & 15, r0 = tid >> 4;
            #pragma unroll
            for (int p = 0; p < 2; p++) {
                int r = r0 + p * 16;
                float4 v;
                if (c4 < 8) v = *(const float4*)(Wq + (size_t)(kt + r) * CQK + c4 * 4);
                else        v = *(const float4*)(Wk + (size_t)(kt + r) * CQK + (c4 - 8) * 4);
                *(float4*)(&Bs[r][c4 * 4]) = v;
            }
        }
        __syncthreads();

        #pragma unroll
        for (int kk = 0; kk < 32; kk++) {
            float a[8];
            #pragma unroll
            for (int i = 0; i < 8; i++) a[i] = As[ty * 8 + i][kk];
            float4 bv4 = *(const float4*)(&Bs[kk][tx * 4]);
            #pragma unroll
            for (int i = 0; i < 8; i++) {
                acc[i][0] += a[i] * bv4.x;
                acc[i][1] += a[i] * bv4.y;
                acc[i][2] += a[i] * bv4.z;
                acc[i][3] += a[i] * bv4.w;
            }
        }

        // fused row-sum pass over the As tile (vbar / xbar)
        #pragma unroll
        for (int j = 0; j < 16; j++) {
            float xv = As[srow][scb + j];
            sx += xv;
            sv = fmaf(wv_s[kt + scb + j], xv, sv);
        }
        __syncthreads();
    }

    // vbar / xbar writeback; vbar hi/lo bf16 split
    sv += __shfl_xor_sync(0xffffffffu, sv, 1);
    sx += __shfl_xor_sync(0xffffffffu, sx, 1);
    if ((tid & 1) == 0) {
        float vb = sv + g_bvbar;
        __nv_bfloat16 h = __float2bfloat16_rn(vb);
        g_vbh[m0 + srow] = h;
        g_vbl[m0 + srow] = __float2bfloat16_rn(vb - __bfloat162float(h));
        g_xbar[m0 + srow] = sx * (1.f / CIN);
    }

    const int c = tx * 4;
    const bool isQ = (c < 32);
    const int c0 = isQ ? c : c - 32;
    float4 bb = isQ ? *(const float4*)(bq + c0) : *(const float4*)(bk + c0);

    #pragma unroll
    for (int i = 0; i < 8; i++) {
        size_t row = (size_t)m0 + ty * 8 + i;
        float v0 = acc[i][0] + bb.x, v1 = acc[i][1] + bb.y;
        float v2 = acc[i][2] + bb.z, v3 = acc[i][3] + bb.w;
        if (isQ) {
            v0 *= LOG2E; v1 *= LOG2E; v2 *= LOG2E; v3 *= LOG2E;
            __half h0 = __float2half_rn(v0), h1 = __float2half_rn(v1);
            __half h2 = __float2half_rn(v2), h3 = __float2half_rn(v3);
            float l0 = v0 - __half2float(h0), l1 = v1 - __half2float(h1);
            float l2 = v2 - __half2float(h2), l3 = v3 - __half2float(h3);
            __half* dst = g_qs + row * QW + c0;
            *(uint2*)(dst)      = make_uint2(pack_h2(v0, v1), pack_h2(v2, v3)); // q_hi
            *(uint2*)(dst + 32) = make_uint2(pack_h2(l0, l1), pack_h2(l2, l3)); // q_lo
        } else {
            __half* dst = g_ks + row * KW + c0;
            *(uint2*)(dst) = make_uint2(pack_h2(v0, v1), pack_h2(v2, v3));      // k_hi
        }
    }
}

// =========================== attention kernel ==============================
// smem: vb_hi(8K) + vb_lo(8K) + two K tiles [128 rows][40 fp16] (80-B pitch)
#define TPITCH   80
#define TILE_B   (128 * TPITCH)      // 10240
#define OFF_VH   0
#define OFF_VL   8192
#define OFF_K0   16384
#define OFF_K1   (OFF_K0 + TILE_B)   // 26624
#define SMEM_TOT (OFF_K1 + TILE_B)   // 36864

__global__ __launch_bounds__(256, 3) void attn_kernel(
    const float* __restrict__ gamma, float* __restrict__ out) {

    extern __shared__ __align__(16) char smem[];
    const uint32_t sb = smem_u32(smem);
    const int tid = threadIdx.x, wid = tid >> 5, lane = tid & 31;
    const int b = blockIdx.y, n0 = blockIdx.x * 128;

    // per-thread cp.async offsets for a 128x32 fp16 tile (512 16B segs, 2/thread)
    int boff[2]; long soff[2];
    #pragma unroll
    for (int t = 0; t < 2; t++) {
        int idx = tid + t * 256;
        int row = idx >> 2, seg = idx & 3;
        boff[t] = row * TPITCH + seg * 16;
        soff[t] = (long)row * KW + seg * 8;
    }

    const __half* ksrc = g_ks + (size_t)b * N_ * KW;

    // prologue: group0 = VH + VL + K0 ; group1 = K1
    #pragma unroll
    for (int t = 0; t < 2; t++) {
        cp_async16(smem + OFF_VH + (tid + t * 256) * 16,
                   g_vbh + (size_t)b * N_ + (tid + t * 256) * 8);
        cp_async16(smem + OFF_VL + (tid + t * 256) * 16,
                   g_vbl + (size_t)b * N_ + (tid + t * 256) * 8);
    }
    #pragma unroll
    for (int t = 0; t < 2; t++) cp_async16(smem + OFF_K0 + boff[t], ksrc + soff[t]);
    CP_COMMIT();
    #pragma unroll
    for (int t = 0; t < 2; t++)
        cp_async16(smem + OFF_K1 + boff[t], ksrc + (size_t)128 * KW + soff[t]);
    CP_COMMIT();

    // A fragments straight from gmem (m16n8k16 A layout), persistent in regs
    // s=0: q_hi k0-15, s=1: q_hi k16-31, s=2: q_lo k0-15, s=3: q_lo k16-31
    uint32_t A[4][4];
    {
        const __half* q0 =
            g_qs + ((size_t)b * N_ + n0 + wid * 16 + (lane >> 2)) * QW + (lane & 3) * 2;
        #pragma unroll
        for (int s = 0; s < 4; s++) {
            A[s][0] = *(const uint32_t*)(q0 + s * 16);
            A[s][1] = *(const uint32_t*)(q0 + s * 16 + 8 * QW);
            A[s][2] = *(const uint32_t*)(q0 + s * 16 + 8);
            A[s][3] = *(const uint32_t*)(q0 + s * 16 + 8 * QW + 8);
        }
    }

    // PV accumulator: C[r][n]: n0/1 = num(hi/lo parts), n2 = den (ones column)
    float c0 = 0.f, c1 = 0.f, c2 = 0.f, c3 = 0.f;

    const int nn = lane >> 2;      // PV B column owned by this lane
    const __nv_bfloat16* vbase =
        (nn == 0) ? (const __nv_bfloat16*)(smem + OFF_VH)
                  : (const __nv_bfloat16*)(smem + OFF_VL);
    const uint32_t bconst = (nn == 2) ? 0x3F803F80u : 0u;   // bf16x2 (1,1) or 0

    const uint32_t kb_lane = (uint32_t)((lane & 7) * TPITCH + (lane >> 3) * 16);

    for (int ci = 0; ci < NCHUNK; ci++) {
        if (ci == NCHUNK - 1) { CP_WAIT(0); } else { CP_WAIT(1); }
        __syncthreads();

        const uint32_t kbase = sb + ((ci & 1) ? OFF_K1 : OFF_K0) + kb_lane;
        const __nv_bfloat16* vc = vbase + ci * 128 + (lane & 3) * 2;

        #pragma unroll
        for (int s = 0; s < 8; s++) {
            // ---- QK for j = 2s and j = 2s+1: 1 LDSM + 4 chained fp16 MMAs ----
            float da0, da1, da2, da3, db0, db1, db2, db3;
            {
                uint32_t r0, r1, r2, r3;
                ldsm_x4(r0, r1, r2, r3, kbase + (2 * s) * (8 * TPITCH));
                mma_f16(da0, da1, da2, da3, A[0][0], A[0][1], A[0][2], A[0][3], r0, r1,
                        0.f, 0.f, 0.f, 0.f);
                mma_f16(da0, da1, da2, da3, A[1][0], A[1][1], A[1][2], A[1][3], r2, r3,
                        da0, da1, da2, da3);
                mma_f16(da0, da1, da2, da3, A[2][0], A[2][1], A[2][2], A[2][3], r0, r1,
                        da0, da1, da2, da3);
                mma_f16(da0, da1, da2, da3, A[3][0], A[3][1], A[3][2], A[3][3], r2, r3,
                        da0, da1, da2, da3);
            }
            {
                uint32_t r0, r1, r2, r3;
                ldsm_x4(r0, r1, r2, r3, kbase + (2 * s + 1) * (8 * TPITCH));
                mma_f16(db0, db1, db2, db3, A[0][0], A[0][1], A[0][2], A[0][3], r0, r1,
                        0.f, 0.f, 0.f, 0.f);
                mma_f16(db0, db1, db2, db3, A[1][0], A[1][1], A[1][2], A[1][3], r2, r3,
                        db0, db1, db2, db3);
                mma_f16(db0, db1, db2, db3, A[2][0], A[2][1], A[2][2], A[2][3], r0, r1,
                        db0, db1, db2, db3);
                mma_f16(db0, db1, db2, db3, A[3][0], A[3][1], A[3][2], A[3][3], r2, r3,
                        db0, db1, db2, db3);
            }

            // ---- softmax numerators as bf16 P fragments ----
            uint32_t a0 = cvt_bf2(ex2f(da1), ex2f(da0));   // row r,   keys 16s+2(l&3)+{0,1}
            uint32_t a1 = cvt_bf2(ex2f(da3), ex2f(da2));   // row r+8
            uint32_t a2 = cvt_bf2(ex2f(db1), ex2f(db0));   // row r,   keys +8
            uint32_t a3 = cvt_bf2(ex2f(db3), ex2f(db2));   // row r+8

            // ---- PV B fragment: cols [vb_hi | vb_lo | 1 | 0...] ----
            uint32_t pb0, pb1;
            if (nn < 2) {
                pb0 = *(const uint32_t*)(vc + 16 * s);
                pb1 = *(const uint32_t*)(vc + 16 * s + 8);
            } else {
                pb0 = bconst; pb1 = bconst;
            }

            mma_bf16(c0, c1, c2, c3, a0, a1, a2, a3, pb0, pb1, c0, c1, c2, c3);
        }

        __syncthreads();
        if (ci + 2 < NCHUNK) {   // refill the buffer chunk ci just finished with
            char* dst = smem + ((ci & 1) ? OFF_K1 : OFF_K0);
            const __half* src = ksrc + (size_t)(ci + 2) * 128 * KW;
            #pragma unroll
            for (int t = 0; t < 2; t++) cp_async16(dst + boff[t], src + soff[t]);
            CP_COMMIT();
        }
    }

    // extraction: lane&3==0 holds num parts (cols 0,1); lane&3==1 holds den (col 2)
    const int base = lane & ~3;
    float den0 = __shfl_sync(0xffffffffu, c0, base + 1);
    float den1 = __shfl_sync(0xffffffffu, c2, base + 1);
    if ((lane & 3) == 0) {
        const float g = gamma[0];
        float num0 = c0 + c1;
        float num1 = c2 + c3;
        int r0 = n0 + wid * 16 + (lane >> 2);
        size_t i0 = (size_t)b * N_ + r0;
        size_t i1 = i0 + 8;
        out[i0] = g * (num0 / den0) + g_xbar[i0];
        out[i1] = g * (num1 / den1) + g_xbar[i1];
    }
}

// ---------------------------------------------------------------------------
extern "C" void kernel_launch(void* const* d_in, const int* in_sizes, int n_in,
                              void* d_out, int out_size) {
    const float* x     = (const float*)d_in[0];
    const float* Wq    = (const float*)d_in[1];
    const float* bq    = (const float*)d_in[2];
    const float* Wk    = (const float*)d_in[3];
    const float* bk    = (const float*)d_in[4];
    const float* Wv    = (const float*)d_in[5];
    const float* bv    = (const float*)d_in[6];
    const float* gamma = (const float*)d_in[7];
    float* out = (float*)d_out;

    prep_kernel<<<32, 256>>>(Wv, bv);
    qk_gemm<<<NROWS / 128, 256>>>(x, Wq, bq, Wk, bk);

    cudaFuncSetAttribute(attn_kernel, cudaFuncAttributeMaxDynamicSharedMemorySize, SMEM_TOT);
    attn_kernel<<<dim3(N_ / 128, B_), 256, SMEM_TOT>>>(gamma, out);
}

// round 9
// speedup vs baseline: 2.2517x; 1.1516x over previous
#include <cuda_runtime.h>
#include <cuda_bf16.h>
#include <cuda_fp16.h>
#include <math.h>
#include <stdint.h>

#define B_    8
#define N_    4096
#define CIN   256
#define CQK   32
#define NROWS (B_ * N_)   // 32768
#define QW    64          // q store: [q_hi(32) | q_lo(32)] fp16
#define KW    32          // k store: k_hi fp16
#define NCHUNK (N_ / 128) // 32
#define LOG2E 1.4426950408889634f

// ---- scratch (device globals; no allocation allowed) ----
__device__ __half g_qs[NROWS * QW];   // 4 MB, pre-scaled by log2e
__device__ __half g_ks[NROWS * KW];   // 2 MB
__device__ __half g_wh[64 * CIN];     // W split hi: [n][k] (n: Wq cols | Wk cols)
__device__ __half g_wl[64 * CIN];     // W split lo
__device__ __nv_bfloat16 g_vbh[NROWS];
__device__ __nv_bfloat16 g_vbl[NROWS];
__device__ float g_xbar[NROWS];
__device__ float g_wvbar[CIN];
__device__ float g_bvbar;

// =========================== PTX helpers ===================================
__device__ __forceinline__ uint32_t smem_u32(const void* p) {
    uint32_t a;
    asm("{ .reg .u64 t; cvta.to.shared.u64 t, %1; cvt.u32.u64 %0, t; }"
        : "=r"(a) : "l"(p));
    return a;
}
__device__ __forceinline__ void cp_async16(void* dst, const void* src) {
    uint32_t d = smem_u32(dst);
    asm volatile("cp.async.cg.shared.global [%0], [%1], 16;" :: "r"(d), "l"(src) : "memory");
}
#define CP_COMMIT()  asm volatile("cp.async.commit_group;" ::: "memory")
#define CP_WAIT(n)   asm volatile("cp.async.wait_group %0;" :: "n"(n) : "memory")

__device__ __forceinline__ void ldsm_x4(uint32_t& r0, uint32_t& r1,
                                        uint32_t& r2, uint32_t& r3, uint32_t a) {
    asm volatile("ldmatrix.sync.aligned.m8n8.x4.shared.b16 {%0,%1,%2,%3}, [%4];"
        : "=r"(r0), "=r"(r1), "=r"(r2), "=r"(r3) : "r"(a));
}
__device__ __forceinline__ void mma_f16(float& d0, float& d1, float& d2, float& d3,
    uint32_t a0, uint32_t a1, uint32_t a2, uint32_t a3,
    uint32_t b0, uint32_t b1,
    float c0, float c1, float c2, float c3) {
    asm volatile("mma.sync.aligned.m16n8k16.row.col.f32.f16.f16.f32 "
        "{%0,%1,%2,%3},{%4,%5,%6,%7},{%8,%9},{%10,%11,%12,%13};"
        : "=f"(d0), "=f"(d1), "=f"(d2), "=f"(d3)
        : "r"(a0), "r"(a1), "r"(a2), "r"(a3), "r"(b0), "r"(b1),
          "f"(c0), "f"(c1), "f"(c2), "f"(c3));
}
__device__ __forceinline__ void mma_bf16(float& d0, float& d1, float& d2, float& d3,
    uint32_t a0, uint32_t a1, uint32_t a2, uint32_t a3,
    uint32_t b0, uint32_t b1,
    float c0, float c1, float c2, float c3) {
    asm volatile("mma.sync.aligned.m16n8k16.row.col.f32.bf16.bf16.f32 "
        "{%0,%1,%2,%3},{%4,%5,%6,%7},{%8,%9},{%10,%11,%12,%13};"
        : "=f"(d0), "=f"(d1), "=f"(d2), "=f"(d3)
        : "r"(a0), "r"(a1), "r"(a2), "r"(a3), "r"(b0), "r"(b1),
          "f"(c0), "f"(c1), "f"(c2), "f"(c3));
}
__device__ __forceinline__ float ex2f(float x) {
    float r;
    asm("ex2.approx.f32 %0, %1;" : "=f"(r) : "f"(x));
    return r;
}
__device__ __forceinline__ uint32_t cvt_bf2(float hi, float lo) {
    uint32_t r;
    asm("cvt.rn.bf16x2.f32 %0, %1, %2;" : "=r"(r) : "f"(hi), "f"(lo));
    return r;
}
__device__ __forceinline__ uint32_t pack_h2(float a, float b) {
    __half2 t = __floats2half2_rn(a, b);
    return *reinterpret_cast<uint32_t*>(&t);
}

// =========================== prep kernel ===================================
// wvbar + bvbar (all CTAs) + W transpose/split to g_wh/g_wl (CTAs 0-7)
__global__ __launch_bounds__(256) void prep_kernel(
    const float* __restrict__ Wv, const float* __restrict__ bv,
    const float* __restrict__ Wq, const float* __restrict__ Wk) {
    const int wid = threadIdx.x >> 5, lane = threadIdx.x & 31;
    const int row = blockIdx.x * 8 + wid;
    const float* wr = Wv + (size_t)row * CIN;
    float s = 0.f;
    #pragma unroll
    for (int j = 0; j < 8; j++) s += wr[lane + j * 32];
    #pragma unroll
    for (int off = 16; off > 0; off >>= 1)
        s += __shfl_xor_sync(0xffffffffu, s, off);
    if (lane == 0) g_wvbar[row] = s * (1.f / CIN);

    if (blockIdx.x == 0 && wid == 0) {
        float t = 0.f;
        #pragma unroll
        for (int j = 0; j < 8; j++) t += bv[lane + j * 32];
        #pragma unroll
        for (int off = 16; off > 0; off >>= 1)
            t += __shfl_xor_sync(0xffffffffu, t, off);
        if (lane == 0) g_bvbar = t * (1.f / CIN);
    }

    // W split: B[n][k] = (n<32 ? Wq[k][n] : Wk[k][n-32]), hi/lo fp16
    if (blockIdx.x < 8) {
        const int n = blockIdx.x * 8 + wid;
        const float* wsrc = (n < 32) ? (Wq + n) : (Wk + n - 32);
        #pragma unroll
        for (int j = 0; j < 8; j++) {
            int k = lane + j * 32;
            float v = wsrc[(size_t)k * CQK];
            __half h = __float2half_rn(v);
            g_wh[n * CIN + k] = h;
            g_wl[n * CIN + k] = __float2half_rn(v - __half2float(h));
        }
    }
}

// ======================= Q/K projection GEMM (tensor core) ==================
// C(32768 x 64) = x @ [Wq|Wk] + bias via exact 3-term fp16 split:
//   x_hi*W_hi + x_lo*W_hi + x_hi*W_lo   (dropped x_lo*W_lo ~ 2^-24)
// Fused: vbar/xbar row sums during conversion. Epilogue: fp16 hi/lo stores.
#define QPITCH 144                    // bytes per 64-col fp16 row (+pad)
#define OFF_XH 0                      // 128 x 144 = 18432
#define OFF_XL 18432
#define OFF_WHS 36864                 // 64 x 144 = 9216
#define OFF_WLS 46080
#define OFF_WVS 55296                 // 256 floats
#define QK_SMEM 56320

__global__ __launch_bounds__(256, 2) void qk_gemm(
    const float* __restrict__ x,
    const float* __restrict__ bq, const float* __restrict__ bk) {

    extern __shared__ __align__(16) char smem[];
    const uint32_t sb = smem_u32(smem);
    const int tid = threadIdx.x, w = tid >> 5, lane = tid & 31;
    const int m0 = blockIdx.x * 128;

    ((float*)(smem + OFF_WVS))[tid] = g_wvbar[tid];
    __syncthreads();

    float c[8][4];
    #pragma unroll
    for (int i = 0; i < 8; i++)
        #pragma unroll
        for (int j = 0; j < 4; j++) c[i][j] = 0.f;
    float sxr[8], svr[8];
    #pragma unroll
    for (int t = 0; t < 8; t++) { sxr[t] = 0.f; svr[t] = 0.f; }

    const uint32_t abh = sb + OFF_XH + (w * 16 + (lane & 15)) * QPITCH + (lane >> 4) * 16;
    const uint32_t abl = sb + OFF_XL + (w * 16 + (lane & 15)) * QPITCH + (lane >> 4) * 16;
    const uint32_t bbh = sb + OFF_WHS + (lane & 7) * QPITCH + (lane >> 3) * 16;
    const uint32_t bbl = sb + OFF_WLS + (lane & 7) * QPITCH + (lane >> 3) * 16;
    const float* wvs = (const float*)(smem + OFF_WVS);

    for (int kc = 0; kc < 4; kc++) {
        // stage W chunk [64 n][64 k]
        #pragma unroll
        for (int t = 0; t < 2; t++) {
            int s2 = t * 256 + tid;
            int n = s2 >> 3, seg = s2 & 7;
            *(uint4*)(smem + OFF_WHS + n * QPITCH + seg * 16) =
                *(const uint4*)(g_wh + n * CIN + kc * 64 + seg * 8);
            *(uint4*)(smem + OFF_WLS + n * QPITCH + seg * 16) =
                *(const uint4*)(g_wl + n * CIN + kc * 64 + seg * 8);
        }
        // convert x chunk [128 rows][64 k] -> fp16 hi/lo; fuse row sums
        #pragma unroll
        for (int t = 0; t < 8; t++) {
            int row = t * 16 + (tid >> 4), seg = tid & 15;
            float4 xv = *(const float4*)(x + (size_t)(m0 + row) * CIN + kc * 64 + seg * 4);
            float4 wv = *(const float4*)(wvs + kc * 64 + seg * 4);
            sxr[t] += (xv.x + xv.y) + (xv.z + xv.w);
            svr[t] = fmaf(xv.x, wv.x, fmaf(xv.y, wv.y,
                     fmaf(xv.z, wv.z, fmaf(xv.w, wv.w, svr[t]))));
            __half h0 = __float2half_rn(xv.x), h1 = __float2half_rn(xv.y);
            __half h2 = __float2half_rn(xv.z), h3 = __float2half_rn(xv.w);
            float l0 = xv.x - __half2float(h0), l1 = xv.y - __half2float(h1);
            float l2 = xv.z - __half2float(h2), l3 = xv.w - __half2float(h3);
            __half2 hh0 = __halves2half2(h0, h1), hh1 = __halves2half2(h2, h3);
            *(uint2*)(smem + OFF_XH + row * QPITCH + seg * 8) =
                make_uint2(*(uint32_t*)&hh0, *(uint32_t*)&hh1);
            *(uint2*)(smem + OFF_XL + row * QPITCH + seg * 8) =
                make_uint2(pack_h2(l0, l1), pack_h2(l2, l3));
        }
        __syncthreads();

        #pragma unroll
        for (int kc2 = 0; kc2 < 2; kc2++) {
            uint32_t ah0[4], ah1[4], al0[4], al1[4];
            ldsm_x4(ah0[0], ah0[1], ah0[2], ah0[3], abh + kc2 * 64);
            ldsm_x4(ah1[0], ah1[1], ah1[2], ah1[3], abh + kc2 * 64 + 32);
            ldsm_x4(al0[0], al0[1], al0[2], al0[3], abl + kc2 * 64);
            ldsm_x4(al1[0], al1[1], al1[2], al1[3], abl + kc2 * 64 + 32);
            #pragma unroll
            for (int nt = 0; nt < 8; nt++) {
                uint32_t bh[4], bl[4];
                ldsm_x4(bh[0], bh[1], bh[2], bh[3], bbh + nt * 8 * QPITCH + kc2 * 64);
                ldsm_x4(bl[0], bl[1], bl[2], bl[3], bbl + nt * 8 * QPITCH + kc2 * 64);
                mma_f16(c[nt][0], c[nt][1], c[nt][2], c[nt][3],
                        ah0[0], ah0[1], ah0[2], ah0[3], bh[0], bh[1],
                        c[nt][0], c[nt][1], c[nt][2], c[nt][3]);
                mma_f16(c[nt][0], c[nt][1], c[nt][2], c[nt][3],
                        ah1[0], ah1[1], ah1[2], ah1[3], bh[2], bh[3],
                        c[nt][0], c[nt][1], c[nt][2], c[nt][3]);
                mma_f16(c[nt][0], c[nt][1], c[nt][2], c[nt][3],
                        al0[0], al0[1], al0[2], al0[3], bh[0], bh[1],
                        c[nt][0], c[nt][1], c[nt][2], c[nt][3]);
                mma_f16(c[nt][0], c[nt][1], c[nt][2], c[nt][3],
                        al1[0], al1[1], al1[2], al1[3], bh[2], bh[3],
                        c[nt][0], c[nt][1], c[nt][2], c[nt][3]);
                mma_f16(c[nt][0], c[nt][1], c[nt][2], c[nt][3],
                        ah0[0], ah0[1], ah0[2], ah0[3], bl[0], bl[1],
                        c[nt][0], c[nt][1], c[nt][2], c[nt][3]);
                mma_f16(c[nt][0], c[nt][1], c[nt][2], c[nt][3],
                        ah1[0], ah1[1], ah1[2], ah1[3], bl[2], bl[3],
                        c[nt][0], c[nt][1], c[nt][2], c[nt][3]);
            }
        }
        __syncthreads();
    }

    // vbar / xbar writeback
    #pragma unroll
    for (int t = 0; t < 8; t++) {
        float sx = sxr[t], sv = svr[t];
        #pragma unroll
        for (int off = 1; off < 16; off <<= 1) {
            sx += __shfl_xor_sync(0xffffffffu, sx, off);
            sv += __shfl_xor_sync(0xffffffffu, sv, off);
        }
        if ((lane & 15) == 0) {
            int row = m0 + t * 16 + (tid >> 4);
            float vb = sv + g_bvbar;
            __nv_bfloat16 h = __float2bfloat16_rn(vb);
            g_vbh[row] = h;
            g_vbl[row] = __float2bfloat16_rn(vb - __bfloat162float(h));
            g_xbar[row] = sx * (1.f / CIN);
        }
    }

    // epilogue: bias, (Q: log2e scale + hi/lo split), stores
    const int r0 = lane >> 2;
    const int cl = (lane & 3) * 2;
    const size_t grow = (size_t)m0 + w * 16 + r0;
    #pragma unroll
    for (int nt = 0; nt < 8; nt++) {
        const int n = nt * 8 + cl;
        if (n < 32) {
            float2 bb = *(const float2*)(bq + n);
            #pragma unroll
            for (int half = 0; half < 2; half++) {
                size_t row = grow + half * 8;
                float v0 = (c[nt][2 * half + 0] + bb.x) * LOG2E;
                float v1 = (c[nt][2 * half + 1] + bb.y) * LOG2E;
                __half h0 = __float2half_rn(v0), h1 = __float2half_rn(v1);
                __half2 hh = __halves2half2(h0, h1);
                *(uint32_t*)(g_qs + row * QW + n) = *(uint32_t*)&hh;
                *(uint32_t*)(g_qs + row * QW + n + 32) =
                    pack_h2(v0 - __half2float(h0), v1 - __half2float(h1));
            }
        } else {
            float2 bb = *(const float2*)(bk + n - 32);
            #pragma unroll
            for (int half = 0; half < 2; half++) {
                size_t row = grow + half * 8;
                *(uint32_t*)(g_ks + row * KW + n - 32) =
                    pack_h2(c[nt][2 * half + 0] + bb.x, c[nt][2 * half + 1] + bb.y);
            }
        }
    }
}

// =========================== attention kernel ==============================
// smem: vb_hi(8K) + vb_lo(8K) + two K tiles [128 rows][40 fp16] (80-B pitch)
#define TPITCH   80
#define TILE_B   (128 * TPITCH)      // 10240
#define OFF_VH   0
#define OFF_VL   8192
#define OFF_K0   16384
#define OFF_K1   (OFF_K0 + TILE_B)   // 26624
#define SMEM_TOT (OFF_K1 + TILE_B)   // 36864

__global__ __launch_bounds__(256, 3) void attn_kernel(
    const float* __restrict__ gamma, float* __restrict__ out) {

    extern __shared__ __align__(16) char smem[];
    const uint32_t sb = smem_u32(smem);
    const int tid = threadIdx.x, wid = tid >> 5, lane = tid & 31;
    const int b = blockIdx.y, n0 = blockIdx.x * 128;

    // per-thread cp.async offsets for a 128x32 fp16 tile (512 16B segs, 2/thread)
    int boff[2]; long soff[2];
    #pragma unroll
    for (int t = 0; t < 2; t++) {
        int idx = tid + t * 256;
        int row = idx >> 2, seg = idx & 3;
        boff[t] = row * TPITCH + seg * 16;
        soff[t] = (long)row * KW + seg * 8;
    }

    const __half* ksrc = g_ks + (size_t)b * N_ * KW;

    // prologue: group0 = VH + VL + K0 ; group1 = K1
    #pragma unroll
    for (int t = 0; t < 2; t++) {
        cp_async16(smem + OFF_VH + (tid + t * 256) * 16,
                   g_vbh + (size_t)b * N_ + (tid + t * 256) * 8);
        cp_async16(smem + OFF_VL + (tid + t * 256) * 16,
                   g_vbl + (size_t)b * N_ + (tid + t * 256) * 8);
    }
    #pragma unroll
    for (int t = 0; t < 2; t++) cp_async16(smem + OFF_K0 + boff[t], ksrc + soff[t]);
    CP_COMMIT();
    #pragma unroll
    for (int t = 0; t < 2; t++)
        cp_async16(smem + OFF_K1 + boff[t], ksrc + (size_t)128 * KW + soff[t]);
    CP_COMMIT();

    // A fragments straight from gmem (m16n8k16 A layout), persistent in regs
    uint32_t A[4][4];
    {
        const __half* q0 =
            g_qs + ((size_t)b * N_ + n0 + wid * 16 + (lane >> 2)) * QW + (lane & 3) * 2;
        #pragma unroll
        for (int s = 0; s < 4; s++) {
            A[s][0] = *(const uint32_t*)(q0 + s * 16);
            A[s][1] = *(const uint32_t*)(q0 + s * 16 + 8 * QW);
            A[s][2] = *(const uint32_t*)(q0 + s * 16 + 8);
            A[s][3] = *(const uint32_t*)(q0 + s * 16 + 8 * QW + 8);
        }
    }

    // PV accumulator: C[r][n]: n0/1 = num(hi/lo parts), n2 = den (ones column)
    float c0 = 0.f, c1 = 0.f, c2 = 0.f, c3 = 0.f;

    const int nn = lane >> 2;
    const __nv_bfloat16* vbase =
        (nn == 0) ? (const __nv_bfloat16*)(smem + OFF_VH)
                  : (const __nv_bfloat16*)(smem + OFF_VL);
    const uint32_t bconst = (nn == 2) ? 0x3F803F80u : 0u;

    const uint32_t kb_lane = (uint32_t)((lane & 7) * TPITCH + (lane >> 3) * 16);

    for (int ci = 0; ci < NCHUNK; ci++) {
        if (ci == NCHUNK - 1) { CP_WAIT(0); } else { CP_WAIT(1); }
        __syncthreads();

        const uint32_t kbase = sb + ((ci & 1) ? OFF_K1 : OFF_K0) + kb_lane;
        const __nv_bfloat16* vc = vbase + ci * 128 + (lane & 3) * 2;

        #pragma unroll
        for (int s = 0; s < 8; s++) {
            float da0, da1, da2, da3, db0, db1, db2, db3;
            {
                uint32_t r0, r1, r2, r3;
                ldsm_x4(r0, r1, r2, r3, kbase + (2 * s) * (8 * TPITCH));
                mma_f16(da0, da1, da2, da3, A[0][0], A[0][1], A[0][2], A[0][3], r0, r1,
                        0.f, 0.f, 0.f, 0.f);
                mma_f16(da0, da1, da2, da3, A[1][0], A[1][1], A[1][2], A[1][3], r2, r3,
                        da0, da1, da2, da3);
                mma_f16(da0, da1, da2, da3, A[2][0], A[2][1], A[2][2], A[2][3], r0, r1,
                        da0, da1, da2, da3);
                mma_f16(da0, da1, da2, da3, A[3][0], A[3][1], A[3][2], A[3][3], r2, r3,
                        da0, da1, da2, da3);
            }
            {
                uint32_t r0, r1, r2, r3;
                ldsm_x4(r0, r1, r2, r3, kbase + (2 * s + 1) * (8 * TPITCH));
                mma_f16(db0, db1, db2, db3, A[0][0], A[0][1], A[0][2], A[0][3], r0, r1,
                        0.f, 0.f, 0.f, 0.f);
                mma_f16(db0, db1, db2, db3, A[1][0], A[1][1], A[1][2], A[1][3], r2, r3,
                        db0, db1, db2, db3);
                mma_f16(db0, db1, db2, db3, A[2][0], A[2][1], A[2][2], A[2][3], r0, r1,
                        db0, db1, db2, db3);
                mma_f16(db0, db1, db2, db3, A[3][0], A[3][1], A[3][2], A[3][3], r2, r3,
                        db0, db1, db2, db3);
            }

            uint32_t a0 = cvt_bf2(ex2f(da1), ex2f(da0));
            uint32_t a1 = cvt_bf2(ex2f(da3), ex2f(da2));
            uint32_t a2 = cvt_bf2(ex2f(db1), ex2f(db0));
            uint32_t a3 = cvt_bf2(ex2f(db3), ex2f(db2));

            uint32_t pb0, pb1;
            if (nn < 2) {
                pb0 = *(const uint32_t*)(vc + 16 * s);
                pb1 = *(const uint32_t*)(vc + 16 * s + 8);
            } else {
                pb0 = bconst; pb1 = bconst;
            }

            mma_bf16(c0, c1, c2, c3, a0, a1, a2, a3, pb0, pb1, c0, c1, c2, c3);
        }

        __syncthreads();
        if (ci + 2 < NCHUNK) {
            char* dst = smem + ((ci & 1) ? OFF_K1 : OFF_K0);
            const __half* src = ksrc + (size_t)(ci + 2) * 128 * KW;
            #pragma unroll
            for (int t = 0; t < 2; t++) cp_async16(dst + boff[t], src + soff[t]);
            CP_COMMIT();
        }
    }

    const int base = lane & ~3;
    float den0 = __shfl_sync(0xffffffffu, c0, base + 1);
    float den1 = __shfl_sync(0xffffffffu, c2, base + 1);
    if ((lane & 3) == 0) {
        const float g = gamma[0];
        float num0 = c0 + c1;
        float num1 = c2 + c3;
        int r0 = n0 + wid * 16 + (lane >> 2);
        size_t i0 = (size_t)b * N_ + r0;
        size_t i1 = i0 + 8;
        out[i0] = g * (num0 / den0) + g_xbar[i0];
        out[i1] = g * (num1 / den1) + g_xbar[i1];
    }
}

// ---------------------------------------------------------------------------
extern "C" void kernel_launch(void* const* d_in, const int* in_sizes, int n_in,
                              void* d_out, int out_size) {
    const float* x     = (const float*)d_in[0];
    const float* Wq    = (const float*)d_in[1];
    const float* bq    = (const float*)d_in[2];
    const float* Wk    = (const float*)d_in[3];
    const float* bk    = (const float*)d_in[4];
    const float* Wv    = (const float*)d_in[5];
    const float* bv    = (const float*)d_in[6];
    const float* gamma = (const float*)d_in[7];
    float* out = (float*)d_out;

    prep_kernel<<<32, 256>>>(Wv, bv, Wq, Wk);

    cudaFuncSetAttribute(qk_gemm, cudaFuncAttributeMaxDynamicSharedMemorySize, QK_SMEM);
    qk_gemm<<<NROWS / 128, 256, QK_SMEM>>>(x, bq, bk);

    cudaFuncSetAttribute(attn_kernel, cudaFuncAttributeMaxDynamicSharedMemorySize, SMEM_TOT);
    attn_kernel<<<dim3(N_ / 128, B_), 256, SMEM_TOT>>>(gamma, out);
}

// round 10
// speedup vs baseline: 2.7350x; 1.2146x over previous
#include <cuda_runtime.h>
#include <cuda_bf16.h>
#include <cuda_fp16.h>
#include <math.h>
#include <stdint.h>

#define B_    8
#define N_    4096
#define CIN   256
#define CQK   32
#define NROWS (B_ * N_)   // 32768
#define QW    32          // q store: fp16 (log2e-scaled)
#define KW    32          // k store: fp16
#define NCHUNK (N_ / 128) // 32
#define LOG2E 1.4426950408889634f

// ---- scratch (device globals; no allocation allowed) ----
__device__ __half g_qs[NROWS * QW];   // 2 MB
__device__ __half g_ks[NROWS * KW];   // 2 MB
__device__ __half g_wh[64 * CIN];     // W split hi: [n][k] (n: Wq cols | Wk cols)
__device__ __half g_wl[64 * CIN];     // W split lo
__device__ __nv_bfloat16 g_vbh[NROWS];
__device__ __nv_bfloat16 g_vbl[NROWS];
__device__ float g_xbar[NROWS];
__device__ float g_wvbar[CIN];
__device__ float g_bvbar;

// =========================== PTX helpers ===================================
__device__ __forceinline__ uint32_t smem_u32(const void* p) {
    uint32_t a;
    asm("{ .reg .u64 t; cvta.to.shared.u64 t, %1; cvt.u32.u64 %0, t; }"
        : "=r"(a) : "l"(p));
    return a;
}
__device__ __forceinline__ void cp_async16(void* dst, const void* src) {
    uint32_t d = smem_u32(dst);
    asm volatile("cp.async.cg.shared.global [%0], [%1], 16;" :: "r"(d), "l"(src) : "memory");
}
#define CP_COMMIT()  asm volatile("cp.async.commit_group;" ::: "memory")
#define CP_WAIT(n)   asm volatile("cp.async.wait_group %0;" :: "n"(n) : "memory")

__device__ __forceinline__ void ldsm_x4(uint32_t& r0, uint32_t& r1,
                                        uint32_t& r2, uint32_t& r3, uint32_t a) {
    asm volatile("ldmatrix.sync.aligned.m8n8.x4.shared.b16 {%0,%1,%2,%3}, [%4];"
        : "=r"(r0), "=r"(r1), "=r"(r2), "=r"(r3) : "r"(a));
}
__device__ __forceinline__ void mma_f16(float& d0, float& d1, float& d2, float& d3,
    uint32_t a0, uint32_t a1, uint32_t a2, uint32_t a3,
    uint32_t b0, uint32_t b1,
    float c0, float c1, float c2, float c3) {
    asm volatile("mma.sync.aligned.m16n8k16.row.col.f32.f16.f16.f32 "
        "{%0,%1,%2,%3},{%4,%5,%6,%7},{%8,%9},{%10,%11,%12,%13};"
        : "=f"(d0), "=f"(d1), "=f"(d2), "=f"(d3)
        : "r"(a0), "r"(a1), "r"(a2), "r"(a3), "r"(b0), "r"(b1),
          "f"(c0), "f"(c1), "f"(c2), "f"(c3));
}
__device__ __forceinline__ void mma_bf16(float& d0, float& d1, float& d2, float& d3,
    uint32_t a0, uint32_t a1, uint32_t a2, uint32_t a3,
    uint32_t b0, uint32_t b1,
    float c0, float c1, float c2, float c3) {
    asm volatile("mma.sync.aligned.m16n8k16.row.col.f32.bf16.bf16.f32 "
        "{%0,%1,%2,%3},{%4,%5,%6,%7},{%8,%9},{%10,%11,%12,%13};"
        : "=f"(d0), "=f"(d1), "=f"(d2), "=f"(d3)
        : "r"(a0), "r"(a1), "r"(a2), "r"(a3), "r"(b0), "r"(b1),
          "f"(c0), "f"(c1), "f"(c2), "f"(c3));
}
__device__ __forceinline__ float ex2f(float x) {
    float r;
    asm("ex2.approx.f32 %0, %1;" : "=f"(r) : "f"(x));
    return r;
}
__device__ __forceinline__ uint32_t cvt_bf2(float hi, float lo) {
    uint32_t r;
    asm("cvt.rn.bf16x2.f32 %0, %1, %2;" : "=r"(r) : "f"(hi), "f"(lo));
    return r;
}
__device__ __forceinline__ uint32_t pack_h2(float a, float b) {
    __half2 t = __floats2half2_rn(a, b);
    return *reinterpret_cast<uint32_t*>(&t);
}

// =========================== prep kernel ===================================
__global__ __launch_bounds__(256) void prep_kernel(
    const float* __restrict__ Wv, const float* __restrict__ bv,
    const float* __restrict__ Wq, const float* __restrict__ Wk) {
    const int wid = threadIdx.x >> 5, lane = threadIdx.x & 31;
    const int row = blockIdx.x * 8 + wid;
    const float* wr = Wv + (size_t)row * CIN;
    float s = 0.f;
    #pragma unroll
    for (int j = 0; j < 8; j++) s += wr[lane + j * 32];
    #pragma unroll
    for (int off = 16; off > 0; off >>= 1)
        s += __shfl_xor_sync(0xffffffffu, s, off);
    if (lane == 0) g_wvbar[row] = s * (1.f / CIN);

    if (blockIdx.x == 0 && wid == 0) {
        float t = 0.f;
        #pragma unroll
        for (int j = 0; j < 8; j++) t += bv[lane + j * 32];
        #pragma unroll
        for (int off = 16; off > 0; off >>= 1)
            t += __shfl_xor_sync(0xffffffffu, t, off);
        if (lane == 0) g_bvbar = t * (1.f / CIN);
    }

    // W split: B[n][k] = (n<32 ? Wq[k][n] : Wk[k][n-32]), hi/lo fp16
    if (blockIdx.x < 8) {
        const int n = blockIdx.x * 8 + wid;
        const float* wsrc = (n < 32) ? (Wq + n) : (Wk + n - 32);
        #pragma unroll
        for (int j = 0; j < 8; j++) {
            int k = lane + j * 32;
            float v = wsrc[(size_t)k * CQK];
            __half h = __float2half_rn(v);
            g_wh[n * CIN + k] = h;
            g_wl[n * CIN + k] = __float2half_rn(v - __half2float(h));
        }
    }
}

// ======================= Q/K projection GEMM (tensor core) ==================
#define QPITCH 144
#define OFF_XH 0
#define OFF_XL 18432
#define OFF_WHS 36864
#define OFF_WLS 46080
#define OFF_WVS 55296
#define QK_SMEM 56320

__global__ __launch_bounds__(256, 2) void qk_gemm(
    const float* __restrict__ x,
    const float* __restrict__ bq, const float* __restrict__ bk) {

    extern __shared__ __align__(16) char smem[];
    const uint32_t sb = smem_u32(smem);
    const int tid = threadIdx.x, w = tid >> 5, lane = tid & 31;
    const int m0 = blockIdx.x * 128;

    ((float*)(smem + OFF_WVS))[tid] = g_wvbar[tid];
    __syncthreads();

    float c[8][4];
    #pragma unroll
    for (int i = 0; i < 8; i++)
        #pragma unroll
        for (int j = 0; j < 4; j++) c[i][j] = 0.f;
    float sxr[8], svr[8];
    #pragma unroll
    for (int t = 0; t < 8; t++) { sxr[t] = 0.f; svr[t] = 0.f; }

    const uint32_t abh = sb + OFF_XH + (w * 16 + (lane & 15)) * QPITCH + (lane >> 4) * 16;
    const uint32_t abl = sb + OFF_XL + (w * 16 + (lane & 15)) * QPITCH + (lane >> 4) * 16;
    const uint32_t bbh = sb + OFF_WHS + (lane & 7) * QPITCH + (lane >> 3) * 16;
    const uint32_t bbl = sb + OFF_WLS + (lane & 7) * QPITCH + (lane >> 3) * 16;
    const float* wvs = (const float*)(smem + OFF_WVS);

    for (int kc = 0; kc < 4; kc++) {
        #pragma unroll
        for (int t = 0; t < 2; t++) {
            int s2 = t * 256 + tid;
            int n = s2 >> 3, seg = s2 & 7;
            *(uint4*)(smem + OFF_WHS + n * QPITCH + seg * 16) =
                *(const uint4*)(g_wh + n * CIN + kc * 64 + seg * 8);
            *(uint4*)(smem + OFF_WLS + n * QPITCH + seg * 16) =
                *(const uint4*)(g_wl + n * CIN + kc * 64 + seg * 8);
        }
        #pragma unroll
        for (int t = 0; t < 8; t++) {
            int row = t * 16 + (tid >> 4), seg = tid & 15;
            float4 xv = *(const float4*)(x + (size_t)(m0 + row) * CIN + kc * 64 + seg * 4);
            float4 wv = *(const float4*)(wvs + kc * 64 + seg * 4);
            sxr[t] += (xv.x + xv.y) + (xv.z + xv.w);
            svr[t] = fmaf(xv.x, wv.x, fmaf(xv.y, wv.y,
                     fmaf(xv.z, wv.z, fmaf(xv.w, wv.w, svr[t]))));
            __half h0 = __float2half_rn(xv.x), h1 = __float2half_rn(xv.y);
            __half h2 = __float2half_rn(xv.z), h3 = __float2half_rn(xv.w);
            float l0 = xv.x - __half2float(h0), l1 = xv.y - __half2float(h1);
            float l2 = xv.z - __half2float(h2), l3 = xv.w - __half2float(h3);
            __half2 hh0 = __halves2half2(h0, h1), hh1 = __halves2half2(h2, h3);
            *(uint2*)(smem + OFF_XH + row * QPITCH + seg * 8) =
                make_uint2(*(uint32_t*)&hh0, *(uint32_t*)&hh1);
            *(uint2*)(smem + OFF_XL + row * QPITCH + seg * 8) =
                make_uint2(pack_h2(l0, l1), pack_h2(l2, l3));
        }
        __syncthreads();

        #pragma unroll
        for (int kc2 = 0; kc2 < 2; kc2++) {
            uint32_t ah0[4], ah1[4], al0[4], al1[4];
            ldsm_x4(ah0[0], ah0[1], ah0[2], ah0[3], abh + kc2 * 64);
            ldsm_x4(ah1[0], ah1[1], ah1[2], ah1[3], abh + kc2 * 64 + 32);
            ldsm_x4(al0[0], al0[1], al0[2], al0[3], abl + kc2 * 64);
            ldsm_x4(al1[0], al1[1], al1[2], al1[3], abl + kc2 * 64 + 32);
            #pragma unroll
            for (int nt = 0; nt < 8; nt++) {
                uint32_t bh[4], bl[4];
                ldsm_x4(bh[0], bh[1], bh[2], bh[3], bbh + nt * 8 * QPITCH + kc2 * 64);
                ldsm_x4(bl[0], bl[1], bl[2], bl[3], bbl + nt * 8 * QPITCH + kc2 * 64);
                mma_f16(c[nt][0], c[nt][1], c[nt][2], c[nt][3],
                        ah0[0], ah0[1], ah0[2], ah0[3], bh[0], bh[1],
                        c[nt][0], c[nt][1], c[nt][2], c[nt][3]);
                mma_f16(c[nt][0], c[nt][1], c[nt][2], c[nt][3],
                        ah1[0], ah1[1], ah1[2], ah1[3], bh[2], bh[3],
                        c[nt][0], c[nt][1], c[nt][2], c[nt][3]);
                mma_f16(c[nt][0], c[nt][1], c[nt][2], c[nt][3],
                        al0[0], al0[1], al0[2], al0[3], bh[0], bh[1],
                        c[nt][0], c[nt][1], c[nt][2], c[nt][3]);
                mma_f16(c[nt][0], c[nt][1], c[nt][2], c[nt][3],
                        al1[0], al1[1], al1[2], al1[3], bh[2], bh[3],
                        c[nt][0], c[nt][1], c[nt][2], c[nt][3]);
                mma_f16(c[nt][0], c[nt][1], c[nt][2], c[nt][3],
                        ah0[0], ah0[1], ah0[2], ah0[3], bl[0], bl[1],
                        c[nt][0], c[nt][1], c[nt][2], c[nt][3]);
                mma_f16(c[nt][0], c[nt][1], c[nt][2], c[nt][3],
                        ah1[0], ah1[1], ah1[2], ah1[3], bl[2], bl[3],
                        c[nt][0], c[nt][1], c[nt][2], c[nt][3]);
            }
        }
        __syncthreads();
    }

    // vbar / xbar writeback
    #pragma unroll
    for (int t = 0; t < 8; t++) {
        float sx = sxr[t], sv = svr[t];
        #pragma unroll
        for (int off = 1; off < 16; off <<= 1) {
            sx += __shfl_xor_sync(0xffffffffu, sx, off);
            sv += __shfl_xor_sync(0xffffffffu, sv, off);
        }
        if ((lane & 15) == 0) {
            int row = m0 + t * 16 + (tid >> 4);
            float vb = sv + g_bvbar;
            __nv_bfloat16 h = __float2bfloat16_rn(vb);
            g_vbh[row] = h;
            g_vbl[row] = __float2bfloat16_rn(vb - __bfloat162float(h));
            g_xbar[row] = sx * (1.f / CIN);
        }
    }

    // epilogue: bias, (Q: log2e scale), fp16 stores
    const int r0 = lane >> 2;
    const int cl = (lane & 3) * 2;
    const size_t grow = (size_t)m0 + w * 16 + r0;
    #pragma unroll
    for (int nt = 0; nt < 8; nt++) {
        const int n = nt * 8 + cl;
        if (n < 32) {
            float2 bb = *(const float2*)(bq + n);
            #pragma unroll
            for (int half = 0; half < 2; half++) {
                size_t row = grow + half * 8;
                *(uint32_t*)(g_qs + row * QW + n) =
                    pack_h2((c[nt][2 * half + 0] + bb.x) * LOG2E,
                            (c[nt][2 * half + 1] + bb.y) * LOG2E);
            }
        } else {
            float2 bb = *(const float2*)(bk + n - 32);
            #pragma unroll
            for (int half = 0; half < 2; half++) {
                size_t row = grow + half * 8;
                *(uint32_t*)(g_ks + row * KW + n - 32) =
                    pack_h2(c[nt][2 * half + 0] + bb.x, c[nt][2 * half + 1] + bb.y);
            }
        }
    }
}

// =========================== attention kernel ==============================
// smem: vb_hi(8K) + vb_lo(8K) + ring-4 K tiles [128 rows][40 fp16] (80-B pitch)
#define TPITCH   80
#define TILE_B   (128 * TPITCH)      // 10240
#define OFF_VH   0
#define OFF_VL   8192
#define OFF_K0   16384
#define SMEM_TOT (OFF_K0 + 4 * TILE_B)  // 57344

__global__ __launch_bounds__(256, 3) void attn_kernel(
    const float* __restrict__ gamma, float* __restrict__ out) {

    extern __shared__ __align__(16) char smem[];
    const uint32_t sb = smem_u32(smem);
    const int tid = threadIdx.x, wid = tid >> 5, lane = tid & 31;
    const int b = blockIdx.y, n0 = blockIdx.x * 128;

    // per-thread cp.async offsets for a 128x32 fp16 tile (512 16B segs, 2/thread)
    int boff[2]; long soff[2];
    #pragma unroll
    for (int t = 0; t < 2; t++) {
        int idx = tid + t * 256;
        int row = idx >> 2, seg = idx & 3;
        boff[t] = row * TPITCH + seg * 16;
        soff[t] = (long)row * KW + seg * 8;
    }

    const __half* ksrc = g_ks + (size_t)b * N_ * KW;

    // prologue: g0 = VH + VL + K0 ; g1 = K1 ; g2 = K2
    #pragma unroll
    for (int t = 0; t < 2; t++) {
        cp_async16(smem + OFF_VH + (tid + t * 256) * 16,
                   g_vbh + (size_t)b * N_ + (tid + t * 256) * 8);
        cp_async16(smem + OFF_VL + (tid + t * 256) * 16,
                   g_vbl + (size_t)b * N_ + (tid + t * 256) * 8);
    }
    #pragma unroll
    for (int t = 0; t < 2; t++) cp_async16(smem + OFF_K0 + boff[t], ksrc + soff[t]);
    CP_COMMIT();
    #pragma unroll
    for (int t = 0; t < 2; t++)
        cp_async16(smem + OFF_K0 + TILE_B + boff[t], ksrc + (size_t)128 * KW + soff[t]);
    CP_COMMIT();
    #pragma unroll
    for (int t = 0; t < 2; t++)
        cp_async16(smem + OFF_K0 + 2 * TILE_B + boff[t],
                   ksrc + (size_t)256 * KW + soff[t]);
    CP_COMMIT();

    // A fragments straight from gmem (m16n8k16 A layout), persistent in regs
    uint32_t A[2][4];
    {
        const __half* q0 =
            g_qs + ((size_t)b * N_ + n0 + wid * 16 + (lane >> 2)) * QW + (lane & 3) * 2;
        #pragma unroll
        for (int s = 0; s < 2; s++) {
            A[s][0] = *(const uint32_t*)(q0 + s * 16);
            A[s][1] = *(const uint32_t*)(q0 + s * 16 + 8 * QW);
            A[s][2] = *(const uint32_t*)(q0 + s * 16 + 8);
            A[s][3] = *(const uint32_t*)(q0 + s * 16 + 8 * QW + 8);
        }
    }

    // PV accumulator: C[r][n]: n0/1 = num(hi/lo parts), n2 = den (ones column)
    float c0 = 0.f, c1 = 0.f, c2 = 0.f, c3 = 0.f;

    const int nn = lane >> 2;
    const __nv_bfloat16* vbase =
        (nn == 0) ? (const __nv_bfloat16*)(smem + OFF_VH)
                  : (const __nv_bfloat16*)(smem + OFF_VL);
    const uint32_t bconst = (nn == 2) ? 0x3F803F80u : 0u;

    const uint32_t kb_lane = (uint32_t)((lane & 7) * TPITCH + (lane >> 3) * 16);

    for (int ci = 0; ci < NCHUNK; ci++) {
        if (ci < NCHUNK - 2)       { CP_WAIT(2); }
        else if (ci == NCHUNK - 2) { CP_WAIT(1); }
        else                       { CP_WAIT(0); }
        __syncthreads();   // chunk ci visible; all warps done with chunk ci-1

        if (ci + 3 < NCHUNK) {   // refill buffer (ci+3)&3 == (ci-1)&3 (just freed)
            char* dst = smem + OFF_K0 + ((ci + 3) & 3) * TILE_B;
            const __half* src = ksrc + (size_t)(ci + 3) * 128 * KW;
            #pragma unroll
            for (int t = 0; t < 2; t++) cp_async16(dst + boff[t], src + soff[t]);
            CP_COMMIT();
        }

        const uint32_t kbase = sb + OFF_K0 + (ci & 3) * TILE_B + kb_lane;
        const __nv_bfloat16* vc = vbase + ci * 128 + (lane & 3) * 2;

        #pragma unroll
        for (int s = 0; s < 8; s++) {
            float da0, da1, da2, da3, db0, db1, db2, db3;
            {
                uint32_t r0, r1, r2, r3;
                ldsm_x4(r0, r1, r2, r3, kbase + (2 * s) * (8 * TPITCH));
                mma_f16(da0, da1, da2, da3, A[0][0], A[0][1], A[0][2], A[0][3], r0, r1,
                        0.f, 0.f, 0.f, 0.f);
                mma_f16(da0, da1, da2, da3, A[1][0], A[1][1], A[1][2], A[1][3], r2, r3,
                        da0, da1, da2, da3);
            }
            {
                uint32_t r0, r1, r2, r3;
                ldsm_x4(r0, r1, r2, r3, kbase + (2 * s + 1) * (8 * TPITCH));
                mma_f16(db0, db1, db2, db3, A[0][0], A[0][1], A[0][2], A[0][3], r0, r1,
                        0.f, 0.f, 0.f, 0.f);
                mma_f16(db0, db1, db2, db3, A[1][0], A[1][1], A[1][2], A[1][3], r2, r3,
                        db0, db1, db2, db3);
            }

            uint32_t a0 = cvt_bf2(ex2f(da1), ex2f(da0));
            uint32_t a1 = cvt_bf2(ex2f(da3), ex2f(da2));
            uint32_t a2 = cvt_bf2(ex2f(db1), ex2f(db0));
            uint32_t a3 = cvt_bf2(ex2f(db3), ex2f(db2));

            uint32_t pb0, pb1;
            if (nn < 2) {
                pb0 = *(const uint32_t*)(vc + 16 * s);
                pb1 = *(const uint32_t*)(vc + 16 * s + 8);
            } else {
                pb0 = bconst; pb1 = bconst;
            }

            mma_bf16(c0, c1, c2, c3, a0, a1, a2, a3, pb0, pb1, c0, c1, c2, c3);
        }
    }

    const int base = lane & ~3;
    float den0 = __shfl_sync(0xffffffffu, c0, base + 1);
    float den1 = __shfl_sync(0xffffffffu, c2, base + 1);
    if ((lane & 3) == 0) {
        const float g = gamma[0];
        float num0 = c0 + c1;
        float num1 = c2 + c3;
        int r0 = n0 + wid * 16 + (lane >> 2);
        size_t i0 = (size_t)b * N_ + r0;
        size_t i1 = i0 + 8;
        out[i0] = g * (num0 / den0) + g_xbar[i0];
        out[i1] = g * (num1 / den1) + g_xbar[i1];
    }
}

// ---------------------------------------------------------------------------
extern "C" void kernel_launch(void* const* d_in, const int* in_sizes, int n_in,
                              void* d_out, int out_size) {
    const float* x     = (const float*)d_in[0];
    const float* Wq    = (const float*)d_in[1];
    const float* bq    = (const float*)d_in[2];
    const float* Wk    = (const float*)d_in[3];
    const float* bk    = (const float*)d_in[4];
    const float* Wv    = (const float*)d_in[5];
    const float* bv    = (const float*)d_in[6];
    const float* gamma = (const float*)d_in[7];
    float* out = (float*)d_out;

    prep_kernel<<<32, 256>>>(Wv, bv, Wq, Wk);

    cudaFuncSetAttribute(qk_gemm, cudaFuncAttributeMaxDynamicSharedMemorySize, QK_SMEM);
    qk_gemm<<<NROWS / 128, 256, QK_SMEM>>>(x, bq, bk);

    cudaFuncSetAttribute(attn_kernel, cudaFuncAttributeMaxDynamicSharedMemorySize, SMEM_TOT);
    attn_kernel<<<dim3(N_ / 128, B_), 256, SMEM_TOT>>>(gamma, out);
}